// round 14
// baseline (speedup 1.0000x reference)
#include <cuda_runtime.h>
#include <cuda_fp16.h>
#include <math.h>

namespace {

constexpr int N = 50000;
constexpr int E = 800000;
constexpr float AVG_D_LOG = 2.8332f;
constexpr float EPS_STD = 1e-5f;
constexpr float EPS_BN = 1e-5f;
constexpr float FLT_BIG = 3.402823466e+38f;
constexpr int SCAN_BLOCKS = (N + 1023) / 1024;   // 49

typedef unsigned long long ull;

__device__ __forceinline__ uint4 ldsm_x4(unsigned addr) {
    uint4 r;
    asm volatile("ldmatrix.sync.aligned.m8n8.x4.shared.b16 {%0,%1,%2,%3}, [%4];"
                 : "=r"(r.x), "=r"(r.y), "=r"(r.z), "=r"(r.w) : "r"(addr));
    return r;
}
__device__ __forceinline__ uint4 ldsm_x4_t(unsigned addr) {
    uint4 r;
    asm volatile("ldmatrix.sync.aligned.m8n8.x4.trans.shared.b16 {%0,%1,%2,%3}, [%4];"
                 : "=r"(r.x), "=r"(r.y), "=r"(r.z), "=r"(r.w) : "r"(addr));
    return r;
}
__device__ __forceinline__ void mma16816(float* d, uint4 a, unsigned b0, unsigned b1) {
    asm volatile(
        "mma.sync.aligned.m16n8k16.row.col.f32.f16.f16.f32 "
        "{%0,%1,%2,%3},{%4,%5,%6,%7},{%8,%9},{%0,%1,%2,%3};"
        : "+f"(d[0]), "+f"(d[1]), "+f"(d[2]), "+f"(d[3])
        : "r"(a.x), "r"(a.y), "r"(a.z), "r"(a.w), "r"(b0), "r"(b1));
}
__device__ __forceinline__ void h8_to_f(uint4 u, float* f) {
    __half2* hp = (__half2*)&u;
#pragma unroll
    for (int q = 0; q < 4; q++) {
        float2 t = __half22float2(hp[q]);
        f[2 * q] = t.x; f[2 * q + 1] = t.y;
    }
}

// ---- scratch (device globals: allocation-free contract) ----
__device__ int g_deg[N];
__device__ int g_offs[N + 1];
__device__ int g_cursor[N];
__device__ __align__(16) int2 g_sp[E];                   // (src, eid) at sorted pos
__device__ int g_btot[SCAN_BLOCKS];
__device__ int g_boff[SCAN_BLOCKS];
__device__ __align__(16) __half g_A[(size_t)N * 128];
__device__ __align__(16) __half g_B[(size_t)N * 128];
__device__ __align__(16) __half g_ce[(size_t)E * 128];   // ORIGINAL edge order
__device__ __align__(16) __half g_aggh[(size_t)N * 256]; // fp16 [mean|max|min|std]
__device__ __align__(16) __half g_aggp[(size_t)N * 256];
__device__ float g_amp[N];
__device__ float g_att[N];
__device__ float g_bnsum[64];
__device__ float g_bnsq[64];

// ---------------- init ----------------
__global__ void k_init() {
    int i = blockIdx.x * blockDim.x + threadIdx.x;
    if (i < N) g_deg[i] = 0;
    if (i < 64) { g_bnsum[i] = 0.f; g_bnsq[i] = 0.f; }
}

// ---------------- degree histogram ----------------
__global__ void k_hist(const int* __restrict__ dst) {
    int e = blockIdx.x * blockDim.x + threadIdx.x;
    if (e < E) atomicAdd(&g_deg[dst[e]], 1);
}

// ---------------- multi-block exclusive scan ----------------
__global__ void k_scan1() {
    __shared__ int ws[32];
    int t = threadIdx.x;
    int lane = t & 31, w = t >> 5;
    int base = blockIdx.x * 1024;
    int v = (base + t < N) ? g_deg[base + t] : 0;
    int x = v;
#pragma unroll
    for (int off = 1; off < 32; off <<= 1) {
        int y = __shfl_up_sync(0xffffffffu, x, off);
        if (lane >= off) x += y;
    }
    if (lane == 31) ws[w] = x;
    __syncthreads();
    if (w == 0) {
        int s = ws[lane];
#pragma unroll
        for (int off = 1; off < 32; off <<= 1) {
            int y = __shfl_up_sync(0xffffffffu, s, off);
            if (lane >= off) s += y;
        }
        ws[lane] = s;
    }
    __syncthreads();
    int incl = x + (w > 0 ? ws[w - 1] : 0);
    if (base + t < N) g_offs[base + t] = incl - v;
    if (t == 1023) g_btot[blockIdx.x] = incl;
}

__global__ void k_scan2() {
    if (threadIdx.x == 0) {
        int acc = 0;
        for (int i = 0; i < SCAN_BLOCKS; i++) {
            g_boff[i] = acc;
            acc += g_btot[i];
        }
    }
}

__global__ void k_scan3() {
    int t = threadIdx.x;
    int base = blockIdx.x * 1024;
    int off = g_boff[blockIdx.x];
    if (base + t < N) {
        int v = g_offs[base + t] + off;
        g_offs[base + t] = v;
        g_cursor[base + t] = v;
    }
    if (blockIdx.x == 0 && t == 0) g_offs[N] = E;
}

// ---------------- scatter: counting sort by dst, packed (src,eid) ----------------
__global__ void k_scatter(const int* __restrict__ dst, const int* __restrict__ src) {
    int e = blockIdx.x * blockDim.x + threadIdx.x;
    if (e < E) {
        int pos = atomicAdd(&g_cursor[dst[e]], 1);
        g_sp[pos] = make_int2(src[e], e);
    }
}

// ---------------- node pre-GEMMs via mma.sync -> fp16 g_A, g_B -------------------
constexpr int XP3 = 40;
constexpr int WP3 = 136;

__global__ void __launch_bounds__(256) k_nodepre(
    const float* __restrict__ h, const float* __restrict__ p,
    const float* __restrict__ Wh, const float* __restrict__ Wp)
{
    __shared__ __align__(16) __half Xs[128 * XP3];
    __shared__ __align__(16) __half Ws[32 * WP3];

    int tid = threadIdx.x;
    int base = blockIdx.x * 128;
    int w = tid >> 5;
    int l = tid & 31;
    int slab = w * 16;
    int r8 = l & 7;
    int mat = l >> 3;

    unsigned xsb = (unsigned)__cvta_generic_to_shared(Xs);
    unsigned wsb = (unsigned)__cvta_generic_to_shared(Ws);

    int xrow = tid >> 1;
    int xc0 = (tid & 1) * 16;
    int wk = tid >> 3;
    int wc0 = (tid & 7) * 16;

    float acc[16][4];

    // =========== phase h: K=128 ===========
#pragma unroll
    for (int j = 0; j < 16; j++)
#pragma unroll
        for (int q = 0; q < 4; q++) acc[j][q] = 0.f;

    for (int t = 0; t < 4; t++) {
        int k0 = t * 32;
        if (t) __syncthreads();
        {
            int n0 = base + xrow;
            __half* xd = Xs + xrow * XP3 + xc0;
            if (n0 < N) {
                const float* rp = h + (size_t)n0 * 128 + k0 + xc0;
#pragma unroll
                for (int q = 0; q < 4; q++) {
                    float4 a = *(const float4*)(rp + q * 4);
                    *(__half2*)(xd + q * 4)     = __floats2half2_rn(a.x, a.y);
                    *(__half2*)(xd + q * 4 + 2) = __floats2half2_rn(a.z, a.w);
                }
            } else {
                uint4 z = make_uint4(0, 0, 0, 0);
                *(uint4*)xd = z; *(uint4*)(xd + 8) = z;
            }
        }
        {
            const float* wr = (wc0 < 64) ? (Wh + (size_t)(k0 + wk) * 64 + wc0)
                                         : (Wh + (size_t)(128 + k0 + wk) * 64 + (wc0 - 64));
            __half* wd = Ws + wk * WP3 + wc0;
#pragma unroll
            for (int q = 0; q < 4; q++) {
                float4 a = *(const float4*)(wr + q * 4);
                *(__half2*)(wd + q * 4)     = __floats2half2_rn(a.x, a.y);
                *(__half2*)(wd + q * 4 + 2) = __floats2half2_rn(a.z, a.w);
            }
        }
        __syncthreads();
#pragma unroll
        for (int kc = 0; kc < 2; kc++) {
            int arow = slab + r8 + ((mat & 1) ? 8 : 0);
            int acol = kc * 16 + ((mat & 2) ? 8 : 0);
            uint4 a = ldsm_x4(xsb + (unsigned)(arow * XP3 + acol) * 2u);
            int bk = kc * 16 + r8 + ((mat & 1) ? 8 : 0);
#pragma unroll
            for (int j = 0; j < 8; j++) {
                int bn = j * 16 + ((mat & 2) ? 8 : 0);
                uint4 b = ldsm_x4_t(wsb + (unsigned)(bk * WP3 + bn) * 2u);
                mma16816(acc[2 * j],     a, b.x, b.y);
                mma16816(acc[2 * j + 1], a, b.z, b.w);
            }
        }
    }
    {
        int r0 = slab + (l >> 2);
        int c0 = (l & 3) * 2;
        int n0 = base + r0, n1 = base + r0 + 8;
        bool v0 = n0 < N, v1 = n1 < N;
#pragma unroll
        for (int j = 0; j < 16; j++) {
            int col = 8 * j + c0;
            __half* d0;
            __half* d1;
            if (col < 64) {
                d0 = g_A + (size_t)n0 * 128 + col;
                d1 = g_A + (size_t)n1 * 128 + col;
            } else {
                d0 = g_B + (size_t)n0 * 128 + (col - 64);
                d1 = g_B + (size_t)n1 * 128 + (col - 64);
            }
            if (v0) *(__half2*)d0 = __floats2half2_rn(acc[j][0], acc[j][1]);
            if (v1) *(__half2*)d1 = __floats2half2_rn(acc[j][2], acc[j][3]);
        }
    }

    // =========== phase p: K=64 ===========
#pragma unroll
    for (int j = 0; j < 16; j++)
#pragma unroll
        for (int q = 0; q < 4; q++) acc[j][q] = 0.f;

    for (int t = 0; t < 2; t++) {
        int k0 = t * 32;
        __syncthreads();
        {
            int n0 = base + xrow;
            __half* xd = Xs + xrow * XP3 + xc0;
            if (n0 < N) {
                const float* rp = p + (size_t)n0 * 64 + k0 + xc0;
#pragma unroll
                for (int q = 0; q < 4; q++) {
                    float4 a = *(const float4*)(rp + q * 4);
                    *(__half2*)(xd + q * 4)     = __floats2half2_rn(a.x, a.y);
                    *(__half2*)(xd + q * 4 + 2) = __floats2half2_rn(a.z, a.w);
                }
            } else {
                uint4 z = make_uint4(0, 0, 0, 0);
                *(uint4*)xd = z; *(uint4*)(xd + 8) = z;
            }
        }
        {
            const float* wr = (wc0 < 64) ? (Wp + (size_t)(k0 + wk) * 64 + wc0)
                                         : (Wp + (size_t)(64 + k0 + wk) * 64 + (wc0 - 64));
            __half* wd = Ws + wk * WP3 + wc0;
#pragma unroll
            for (int q = 0; q < 4; q++) {
                float4 a = *(const float4*)(wr + q * 4);
                *(__half2*)(wd + q * 4)     = __floats2half2_rn(a.x, a.y);
                *(__half2*)(wd + q * 4 + 2) = __floats2half2_rn(a.z, a.w);
            }
        }
        __syncthreads();
#pragma unroll
        for (int kc = 0; kc < 2; kc++) {
            int arow = slab + r8 + ((mat & 1) ? 8 : 0);
            int acol = kc * 16 + ((mat & 2) ? 8 : 0);
            uint4 a = ldsm_x4(xsb + (unsigned)(arow * XP3 + acol) * 2u);
            int bk = kc * 16 + r8 + ((mat & 1) ? 8 : 0);
#pragma unroll
            for (int j = 0; j < 8; j++) {
                int bn = j * 16 + ((mat & 2) ? 8 : 0);
                uint4 b = ldsm_x4_t(wsb + (unsigned)(bk * WP3 + bn) * 2u);
                mma16816(acc[2 * j],     a, b.x, b.y);
                mma16816(acc[2 * j + 1], a, b.z, b.w);
            }
        }
    }
    {
        int r0 = slab + (l >> 2);
        int c0 = (l & 3) * 2;
        int n0 = base + r0, n1 = base + r0 + 8;
        bool v0 = n0 < N, v1 = n1 < N;
#pragma unroll
        for (int j = 0; j < 16; j++) {
            int col = 8 * j + c0;
            __half* d0;
            __half* d1;
            if (col < 64) {
                d0 = g_A + (size_t)n0 * 128 + 64 + col;
                d1 = g_A + (size_t)n1 * 128 + 64 + col;
            } else {
                d0 = g_B + (size_t)n0 * 128 + col;
                d1 = g_B + (size_t)n1 * 128 + col;
            }
            if (v0) *(__half2*)d0 = __floats2half2_rn(acc[j][0], acc[j][1]);
            if (v1) *(__half2*)d1 = __floats2half2_rn(acc[j][2], acc[j][3]);
        }
    }
}

// ---------------- edge-feature GEMM via mma.sync (tensor cores) ------------------
constexpr int XP = 40;
constexpr int WP = 136;

__global__ void __launch_bounds__(256) k_edgeE(
    const float* __restrict__ ef,
    const float* __restrict__ Wh, const float* __restrict__ bh,
    const float* __restrict__ Wp, const float* __restrict__ bp)
{
    __shared__ __align__(16) __half Xs[128 * XP];
    __shared__ __align__(16) __half Ws[32 * WP];
    __shared__ float bias[128];

    int tid = threadIdx.x;
    int base = blockIdx.x * 128;
    int w = tid >> 5;
    int l = tid & 31;

    {
        int row = tid >> 1;
        int c0 = (tid & 1) * 16;
        const float* rowp = ef + (size_t)(base + row) * 32 + c0;
        __half* xd = Xs + row * XP + c0;
#pragma unroll
        for (int q = 0; q < 4; q++) {
            float4 a = *(const float4*)(rowp + q * 4);
            *(__half2*)(xd + q * 4)     = __floats2half2_rn(a.x, a.y);
            *(__half2*)(xd + q * 4 + 2) = __floats2half2_rn(a.z, a.w);
        }
    }
    {
        int k = tid >> 3;
        int c0 = (tid & 7) * 16;
        const float* wr = (c0 < 64) ? (Wh + (size_t)(256 + k) * 64 + c0)
                                    : (Wp + (size_t)(128 + k) * 64 + (c0 - 64));
        __half* wd = Ws + k * WP + c0;
#pragma unroll
        for (int q = 0; q < 4; q++) {
            float4 a = *(const float4*)(wr + q * 4);
            *(__half2*)(wd + q * 4)     = __floats2half2_rn(a.x, a.y);
            *(__half2*)(wd + q * 4 + 2) = __floats2half2_rn(a.z, a.w);
        }
    }
    if (tid < 128) bias[tid] = (tid < 64) ? bh[tid] : bp[tid - 64];
    __syncthreads();

    float acc[16][4];
#pragma unroll
    for (int j = 0; j < 16; j++)
#pragma unroll
        for (int q = 0; q < 4; q++) acc[j][q] = 0.f;

    int slab = w * 16;
    int r8 = l & 7;
    int mat = l >> 3;

    unsigned xsbase = (unsigned)__cvta_generic_to_shared(Xs);
    unsigned wsbase = (unsigned)__cvta_generic_to_shared(Ws);

#pragma unroll
    for (int kc = 0; kc < 2; kc++) {
        int arow = slab + r8 + ((mat & 1) ? 8 : 0);
        int acol = kc * 16 + ((mat & 2) ? 8 : 0);
        uint4 a = ldsm_x4(xsbase + (unsigned)(arow * XP + acol) * 2u);
#pragma unroll
        for (int j = 0; j < 8; j++) {
            int bk = kc * 16 + r8 + ((mat & 1) ? 8 : 0);
            int bn = j * 16 + ((mat & 2) ? 8 : 0);
            uint4 b = ldsm_x4_t(wsbase + (unsigned)(bk * WP + bn) * 2u);
            mma16816(acc[2 * j],     a, b.x, b.y);
            mma16816(acc[2 * j + 1], a, b.z, b.w);
        }
    }

    int r0 = slab + (l >> 2);
    int c0 = (l & 3) * 2;
    __half* out0 = g_ce + (size_t)(base + r0) * 128;
    __half* out1 = g_ce + (size_t)(base + r0 + 8) * 128;
#pragma unroll
    for (int j = 0; j < 16; j++) {
        int col = 8 * j + c0;
        float bz0 = bias[col], bz1 = bias[col + 1];
        *(__half2*)(out0 + col) = __floats2half2_rn(acc[j][0] + bz0, acc[j][1] + bz1);
        *(__half2*)(out1 + col) = __floats2half2_rn(acc[j][2] + bz0, acc[j][3] + bz1);
    }
}

// ---------------- fused message + PNA aggregation (half-warp edge parity) --------
// Lane l owns 8 consecutive halfs at offset 8*(l&15); processes edges of parity l>>4.
// Per 2 edges: 1 x 16B ce load + 1 x 16B A load per lane. shfl_xor(16) merges halves.
__global__ void k_agg() {
    int warp = (blockIdx.x * blockDim.x + threadIdx.x) >> 5;
    int l = threadIdx.x & 31;
    if (warp >= N) return;
    int n = warp;
    int s0 = g_offs[n];
    int s1 = g_offs[n + 1];
    int d = s1 - s0;

    int half = l >> 4;
    int f8 = (l & 15) * 8;     // half offset of lane's 8 features

    float b[8];
    h8_to_f(*(const uint4*)(g_B + (size_t)n * 128 + f8), b);

    float sm[8], sq[8], mx[8], mn[8];
#pragma unroll
    for (int j = 0; j < 8; j++) {
        sm[j] = 0.f; sq[j] = 0.f; mx[j] = -FLT_BIG; mn[j] = FLT_BIG;
    }

    for (int i = s0 + half; i < s1; i += 2) {
        int2 sp = g_sp[i];
        uint4 uc = *(const uint4*)(g_ce + (size_t)sp.y * 128 + f8);
        uint4 ua = *(const uint4*)(g_A + (size_t)sp.x * 128 + f8);
        float c[8], a[8];
        h8_to_f(uc, c);
        h8_to_f(ua, a);
#pragma unroll
        for (int j = 0; j < 8; j++) {
            float v = c[j] + a[j] + b[j];
            sm[j] += v; sq[j] += v * v;
            mx[j] = fmaxf(mx[j], v);
            mn[j] = fminf(mn[j], v);
        }
    }

    // merge parity halves
#pragma unroll
    for (int j = 0; j < 8; j++) {
        sm[j] += __shfl_xor_sync(0xffffffffu, sm[j], 16);
        sq[j] += __shfl_xor_sync(0xffffffffu, sq[j], 16);
        mx[j] = fmaxf(mx[j], __shfl_xor_sync(0xffffffffu, mx[j], 16));
        mn[j] = fminf(mn[j], __shfl_xor_sync(0xffffffffu, mn[j], 16));
    }

    float degc = fmaxf((float)d, 1.f);
    float inv = 1.f / degc;
    bool has = d > 0;
    float logd = has ? logf((float)d + 1.f) : 1.f;
    float amp = logd / AVG_D_LOG;
    float att = AVG_D_LOG / logd;
    if (l == 0) { g_amp[n] = amp; g_att[n] = att; }

    if (l < 16) {
        __half* o = (f8 < 64) ? (g_aggh + (size_t)n * 256) : (g_aggp + (size_t)n * 256);
        int f = f8 & 63;
        __half2 t[4];
#pragma unroll
        for (int q = 0; q < 4; q++) {
            float m0 = sm[2 * q] * inv, m1 = sm[2 * q + 1] * inv;
            t[q] = __floats2half2_rn(m0, m1);
        }
        *(uint4*)(o + f) = *(uint4*)t;
#pragma unroll
        for (int q = 0; q < 4; q++) {
            float v0 = has ? mx[2 * q] : 0.f, v1 = has ? mx[2 * q + 1] : 0.f;
            t[q] = __floats2half2_rn(v0, v1);
        }
        *(uint4*)(o + 64 + f) = *(uint4*)t;
#pragma unroll
        for (int q = 0; q < 4; q++) {
            float v0 = has ? mn[2 * q] : 0.f, v1 = has ? mn[2 * q + 1] : 0.f;
            t[q] = __floats2half2_rn(v0, v1);
        }
        *(uint4*)(o + 128 + f) = *(uint4*)t;
#pragma unroll
        for (int q = 0; q < 4; q++) {
            float m0 = sm[2 * q] * inv, m1 = sm[2 * q + 1] * inv;
            float v0 = sqrtf(fmaxf(sq[2 * q] * inv - m0 * m0, 0.f) + EPS_STD);
            float v1 = sqrtf(fmaxf(sq[2 * q + 1] * inv - m1 * m1, 0.f) + EPS_STD);
            t[q] = __floats2half2_rn(v0, v1);
        }
        *(uint4*)(o + 192 + f) = *(uint4*)t;
    }
}

// ---------------- node GEMMs via mma.sync: 3 rails + fused BN stats -------------
constexpr int XP2 = 40;
constexpr int WP2 = 72;

__global__ void __launch_bounds__(256) k_nodegemm(
    const float* __restrict__ h, const float* __restrict__ p,
    const float* __restrict__ snorm,
    const float* __restrict__ Woh, const float* __restrict__ boh,
    const float* __restrict__ Wop, const float* __restrict__ bop,
    float* __restrict__ out)
{
    __shared__ __align__(16) __half Xs[128 * XP2];
    __shared__ __align__(16) __half Ws[3][32 * WP2];
    __shared__ float sbias[64];
    __shared__ float s_amp[128], s_att[128], s_sn[128];
    __shared__ float sbn[64], sbq[64];

    int tid = threadIdx.x;
    int base = blockIdx.x * 128;
    int w = tid >> 5;
    int l = tid & 31;
    int slab = w * 16;
    int r8 = l & 7;
    int mat = l >> 3;

    if (tid < 128) {
        int n0 = base + tid;
        bool ok = n0 < N;
        s_amp[tid] = ok ? g_amp[n0] : 0.f;
        s_att[tid] = ok ? g_att[n0] : 0.f;
        s_sn[tid]  = ok ? snorm[n0] : 0.f;
    }
    if (tid < 64) { sbn[tid] = 0.f; sbq[tid] = 0.f; sbias[tid] = boh[tid]; }

    unsigned xsb = (unsigned)__cvta_generic_to_shared(Xs);
    unsigned wsb0 = (unsigned)__cvta_generic_to_shared(&Ws[0][0]);
    unsigned wsb1 = (unsigned)__cvta_generic_to_shared(&Ws[1][0]);
    unsigned wsb2 = (unsigned)__cvta_generic_to_shared(&Ws[2][0]);

    float accI[8][4], accA[8][4], accT[8][4];

    int xrow = tid >> 1;
    int xc0 = (tid & 1) * 16;
    int wk = (tid * 8) >> 6;
    int wn = (tid * 8) & 63;

    // ================= phase H =================
#pragma unroll
    for (int j = 0; j < 8; j++)
#pragma unroll
        for (int q = 0; q < 4; q++) { accI[j][q] = 0.f; accA[j][q] = 0.f; accT[j][q] = 0.f; }

    for (int t = 0; t < 12; t++) {
        int k0 = t * 32;
        bool isAgg = (t >= 4);
        __syncthreads();
        {
            int n0 = base + xrow;
            __half* xd = Xs + xrow * XP2 + xc0;
            if (n0 < N) {
                if (!isAgg) {
                    const float* rp = h + (size_t)n0 * 128 + k0 + xc0;
#pragma unroll
                    for (int q = 0; q < 4; q++) {
                        float4 a = *(const float4*)(rp + q * 4);
                        *(__half2*)(xd + q * 4)     = __floats2half2_rn(a.x, a.y);
                        *(__half2*)(xd + q * 4 + 2) = __floats2half2_rn(a.z, a.w);
                    }
                } else {
                    const __half* rp = g_aggh + (size_t)n0 * 256 + (k0 - 128) + xc0;
                    *(uint4*)xd       = *(const uint4*)rp;
                    *(uint4*)(xd + 8) = *(const uint4*)(rp + 8);
                }
            } else {
                uint4 z = make_uint4(0, 0, 0, 0);
                *(uint4*)xd = z; *(uint4*)(xd + 8) = z;
            }
        }
        {
            if (isAgg) {
                int aggk = k0 - 128;
                const float* wI = Woh + (size_t)(128 + aggk + wk) * 64 + wn;
                const float* wA = Woh + (size_t)(384 + aggk + wk) * 64 + wn;
                const float* wT = Woh + (size_t)(640 + aggk + wk) * 64 + wn;
                __half* dI = &Ws[0][wk * WP2 + wn];
                __half* dA = &Ws[1][wk * WP2 + wn];
                __half* dT = &Ws[2][wk * WP2 + wn];
#pragma unroll
                for (int q = 0; q < 2; q++) {
                    float4 a = *(const float4*)(wI + q * 4);
                    *(__half2*)(dI + q * 4)     = __floats2half2_rn(a.x, a.y);
                    *(__half2*)(dI + q * 4 + 2) = __floats2half2_rn(a.z, a.w);
                    a = *(const float4*)(wA + q * 4);
                    *(__half2*)(dA + q * 4)     = __floats2half2_rn(a.x, a.y);
                    *(__half2*)(dA + q * 4 + 2) = __floats2half2_rn(a.z, a.w);
                    a = *(const float4*)(wT + q * 4);
                    *(__half2*)(dT + q * 4)     = __floats2half2_rn(a.x, a.y);
                    *(__half2*)(dT + q * 4 + 2) = __floats2half2_rn(a.z, a.w);
                }
            } else {
                const float* wI = Woh + (size_t)(k0 + wk) * 64 + wn;
                __half* dI = &Ws[0][wk * WP2 + wn];
#pragma unroll
                for (int q = 0; q < 2; q++) {
                    float4 a = *(const float4*)(wI + q * 4);
                    *(__half2*)(dI + q * 4)     = __floats2half2_rn(a.x, a.y);
                    *(__half2*)(dI + q * 4 + 2) = __floats2half2_rn(a.z, a.w);
                }
            }
        }
        __syncthreads();
#pragma unroll
        for (int kc = 0; kc < 2; kc++) {
            int arow = slab + r8 + ((mat & 1) ? 8 : 0);
            int acol = kc * 16 + ((mat & 2) ? 8 : 0);
            uint4 a = ldsm_x4(xsb + (unsigned)(arow * XP2 + acol) * 2u);
            int bk = kc * 16 + r8 + ((mat & 1) ? 8 : 0);
#pragma unroll
            for (int j = 0; j < 4; j++) {
                int bn = j * 16 + ((mat & 2) ? 8 : 0);
                unsigned boff = (unsigned)(bk * WP2 + bn) * 2u;
                uint4 bI = ldsm_x4_t(wsb0 + boff);
                mma16816(accI[2 * j],     a, bI.x, bI.y);
                mma16816(accI[2 * j + 1], a, bI.z, bI.w);
                if (isAgg) {
                    uint4 bA = ldsm_x4_t(wsb1 + boff);
                    mma16816(accA[2 * j],     a, bA.x, bA.y);
                    mma16816(accA[2 * j + 1], a, bA.z, bA.w);
                    uint4 bT = ldsm_x4_t(wsb2 + boff);
                    mma16816(accT[2 * j],     a, bT.x, bT.y);
                    mma16816(accT[2 * j + 1], a, bT.z, bT.w);
                }
            }
        }
    }
    {
        int r0 = slab + (l >> 2);
        int c0l = (l & 3) * 2;
        int n0 = base + r0, n1 = base + r0 + 8;
        bool v0 = n0 < N, v1 = n1 < N;
        float amp0 = s_amp[r0], att0 = s_att[r0], sn0 = s_sn[r0];
        float amp1 = s_amp[r0 + 8], att1 = s_att[r0 + 8], sn1 = s_sn[r0 + 8];
#pragma unroll
        for (int j = 0; j < 8; j++) {
            int col = 8 * j + c0l;
            float b0 = sbias[col], b1 = sbias[col + 1];
            float y00 = (accI[j][0] + amp0 * accA[j][0] + att0 * accT[j][0] + b0) * sn0;
            float y01 = (accI[j][1] + amp0 * accA[j][1] + att0 * accT[j][1] + b1) * sn0;
            float y10 = (accI[j][2] + amp1 * accA[j][2] + att1 * accT[j][2] + b0) * sn1;
            float y11 = (accI[j][3] + amp1 * accA[j][3] + att1 * accT[j][3] + b1) * sn1;
            float ss0 = 0.f, ss1 = 0.f, qq0 = 0.f, qq1 = 0.f;
            if (v0) {
                *(float2*)&out[(size_t)n0 * 64 + col] = make_float2(y00, y01);
                ss0 += y00; ss1 += y01; qq0 += y00 * y00; qq1 += y01 * y01;
            }
            if (v1) {
                *(float2*)&out[(size_t)n1 * 64 + col] = make_float2(y10, y11);
                ss0 += y10; ss1 += y11; qq0 += y10 * y10; qq1 += y11 * y11;
            }
            atomicAdd(&sbn[col], ss0); atomicAdd(&sbn[col + 1], ss1);
            atomicAdd(&sbq[col], qq0); atomicAdd(&sbq[col + 1], qq1);
        }
    }
    __syncthreads();
    if (tid < 64) {
        atomicAdd(&g_bnsum[tid], sbn[tid]);
        atomicAdd(&g_bnsq[tid], sbq[tid]);
        sbias[tid] = bop[tid];
    }

    // ================= phase P =================
#pragma unroll
    for (int j = 0; j < 8; j++)
#pragma unroll
        for (int q = 0; q < 4; q++) { accI[j][q] = 0.f; accA[j][q] = 0.f; accT[j][q] = 0.f; }

    for (int t = 0; t < 10; t++) {
        int k0 = t * 32;
        bool isAgg = (t >= 2);
        __syncthreads();
        {
            int n0 = base + xrow;
            __half* xd = Xs + xrow * XP2 + xc0;
            if (n0 < N) {
                if (!isAgg) {
                    const float* rp = p + (size_t)n0 * 64 + k0 + xc0;
#pragma unroll
                    for (int q = 0; q < 4; q++) {
                        float4 a = *(const float4*)(rp + q * 4);
                        *(__half2*)(xd + q * 4)     = __floats2half2_rn(a.x, a.y);
                        *(__half2*)(xd + q * 4 + 2) = __floats2half2_rn(a.z, a.w);
                    }
                } else {
                    const __half* rp = g_aggp + (size_t)n0 * 256 + (k0 - 64) + xc0;
                    *(uint4*)xd       = *(const uint4*)rp;
                    *(uint4*)(xd + 8) = *(const uint4*)(rp + 8);
                }
            } else {
                uint4 z = make_uint4(0, 0, 0, 0);
                *(uint4*)xd = z; *(uint4*)(xd + 8) = z;
            }
        }
        {
            if (isAgg) {
                int aggk = k0 - 64;
                const float* wI = Wop + (size_t)(64 + aggk + wk) * 64 + wn;
                const float* wA = Wop + (size_t)(320 + aggk + wk) * 64 + wn;
                const float* wT = Wop + (size_t)(576 + aggk + wk) * 64 + wn;
                __half* dI = &Ws[0][wk * WP2 + wn];
                __half* dA = &Ws[1][wk * WP2 + wn];
                __half* dT = &Ws[2][wk * WP2 + wn];
#pragma unroll
                for (int q = 0; q < 2; q++) {
                    float4 a = *(const float4*)(wI + q * 4);
                    *(__half2*)(dI + q * 4)     = __floats2half2_rn(a.x, a.y);
                    *(__half2*)(dI + q * 4 + 2) = __floats2half2_rn(a.z, a.w);
                    a = *(const float4*)(wA + q * 4);
                    *(__half2*)(dA + q * 4)     = __floats2half2_rn(a.x, a.y);
                    *(__half2*)(dA + q * 4 + 2) = __floats2half2_rn(a.z, a.w);
                    a = *(const float4*)(wT + q * 4);
                    *(__half2*)(dT + q * 4)     = __floats2half2_rn(a.x, a.y);
                    *(__half2*)(dT + q * 4 + 2) = __floats2half2_rn(a.z, a.w);
                }
            } else {
                const float* wI = Wop + (size_t)(k0 + wk) * 64 + wn;
                __half* dI = &Ws[0][wk * WP2 + wn];
#pragma unroll
                for (int q = 0; q < 2; q++) {
                    float4 a = *(const float4*)(wI + q * 4);
                    *(__half2*)(dI + q * 4)     = __floats2half2_rn(a.x, a.y);
                    *(__half2*)(dI + q * 4 + 2) = __floats2half2_rn(a.z, a.w);
                }
            }
        }
        __syncthreads();
#pragma unroll
        for (int kc = 0; kc < 2; kc++) {
            int arow = slab + r8 + ((mat & 1) ? 8 : 0);
            int acol = kc * 16 + ((mat & 2) ? 8 : 0);
            uint4 a = ldsm_x4(xsb + (unsigned)(arow * XP2 + acol) * 2u);
            int bk = kc * 16 + r8 + ((mat & 1) ? 8 : 0);
#pragma unroll
            for (int j = 0; j < 4; j++) {
                int bn = j * 16 + ((mat & 2) ? 8 : 0);
                unsigned boff = (unsigned)(bk * WP2 + bn) * 2u;
                uint4 bI = ldsm_x4_t(wsb0 + boff);
                mma16816(accI[2 * j],     a, bI.x, bI.y);
                mma16816(accI[2 * j + 1], a, bI.z, bI.w);
                if (isAgg) {
                    uint4 bA = ldsm_x4_t(wsb1 + boff);
                    mma16816(accA[2 * j],     a, bA.x, bA.y);
                    mma16816(accA[2 * j + 1], a, bA.z, bA.w);
                    uint4 bT = ldsm_x4_t(wsb2 + boff);
                    mma16816(accT[2 * j],     a, bT.x, bT.y);
                    mma16816(accT[2 * j + 1], a, bT.z, bT.w);
                }
            }
        }
    }
    {
        int r0 = slab + (l >> 2);
        int c0l = (l & 3) * 2;
        int n0 = base + r0, n1 = base + r0 + 8;
        float amp0 = s_amp[r0], att0 = s_att[r0];
        float amp1 = s_amp[r0 + 8], att1 = s_att[r0 + 8];
        float* outp = out + (size_t)N * 64;
#pragma unroll
        for (int j = 0; j < 8; j++) {
            int col = 8 * j + c0l;
            float b0 = sbias[col], b1 = sbias[col + 1];
            float y00 = accI[j][0] + amp0 * accA[j][0] + att0 * accT[j][0] + b0;
            float y01 = accI[j][1] + amp0 * accA[j][1] + att0 * accT[j][1] + b1;
            float y10 = accI[j][2] + amp1 * accA[j][2] + att1 * accT[j][2] + b0;
            float y11 = accI[j][3] + amp1 * accA[j][3] + att1 * accT[j][3] + b1;
            if (n0 < N) *(float2*)&outp[(size_t)n0 * 64 + col] = make_float2(y00, y01);
            if (n1 < N) *(float2*)&outp[(size_t)n1 * 64 + col] = make_float2(y10, y11);
        }
    }
}

// ---------------- batchnorm apply (float4 vectorized) ----------------
__global__ void k_bnapply(float* __restrict__ out,
                          const float* __restrict__ gamma,
                          const float* __restrict__ beta) {
    int i = blockIdx.x * blockDim.x + threadIdx.x;
    if (i >= N * 16) return;
    int f = (i & 15) * 4;
    const float invN = 1.f / (float)N;
    float4 su = *(const float4*)&g_bnsum[f];
    float4 qu = *(const float4*)&g_bnsq[f];
    float4 ga = *(const float4*)&gamma[f];
    float4 be = *(const float4*)&beta[f];
    float4 mu = make_float4(su.x * invN, su.y * invN, su.z * invN, su.w * invN);
    float4 rs = make_float4(
        rsqrtf(qu.x * invN - mu.x * mu.x + EPS_BN),
        rsqrtf(qu.y * invN - mu.y * mu.y + EPS_BN),
        rsqrtf(qu.z * invN - mu.z * mu.z + EPS_BN),
        rsqrtf(qu.w * invN - mu.w * mu.w + EPS_BN));
    float4 x = *(float4*)&out[(size_t)i * 4];
    x.x = (x.x - mu.x) * rs.x * ga.x + be.x;
    x.y = (x.y - mu.y) * rs.y * ga.y + be.y;
    x.z = (x.z - mu.z) * rs.z * ga.z + be.z;
    x.w = (x.w - mu.w) * rs.w * ga.w + be.w;
    *(float4*)&out[(size_t)i * 4] = x;
}

} // namespace

extern "C" void kernel_launch(void* const* d_in, const int* in_sizes, int n_in,
                              void* d_out, int out_size) {
    const float* h     = (const float*)d_in[0];
    const float* p     = (const float*)d_in[1];
    const float* e     = (const float*)d_in[2];
    const int*   src   = (const int*)d_in[3];
    const int*   dst   = (const int*)d_in[4];
    const float* snorm = (const float*)d_in[5];
    const float* Wph   = (const float*)d_in[6];
    const float* bph   = (const float*)d_in[7];
    const float* Wpp   = (const float*)d_in[8];
    const float* bpp   = (const float*)d_in[9];
    const float* Woh   = (const float*)d_in[10];
    const float* boh   = (const float*)d_in[11];
    const float* Wop   = (const float*)d_in[12];
    const float* bop   = (const float*)d_in[13];
    const float* gamma = (const float*)d_in[14];
    const float* beta  = (const float*)d_in[15];
    float* out = (float*)d_out;

    static cudaStream_t s_pre = nullptr, s_edge = nullptr;
    static cudaEvent_t ev_fork = nullptr, ev_pre = nullptr, ev_edge = nullptr;
    if (s_pre == nullptr) {
        cudaStreamCreateWithFlags(&s_pre, cudaStreamNonBlocking);
        cudaStreamCreateWithFlags(&s_edge, cudaStreamNonBlocking);
        cudaEventCreateWithFlags(&ev_fork, cudaEventDisableTiming);
        cudaEventCreateWithFlags(&ev_pre, cudaEventDisableTiming);
        cudaEventCreateWithFlags(&ev_edge, cudaEventDisableTiming);
    }

    cudaEventRecord(ev_fork, 0);
    cudaStreamWaitEvent(s_pre, ev_fork, 0);
    cudaStreamWaitEvent(s_edge, ev_fork, 0);

    k_nodepre<<<(N + 127) / 128, 256, 0, s_pre>>>(h, p, Wph, Wpp);
    cudaEventRecord(ev_pre, s_pre);

    k_edgeE<<<E / 128, 256, 0, s_edge>>>(e, Wph, bph, Wpp, bpp);
    cudaEventRecord(ev_edge, s_edge);

    k_init<<<(N + 255) / 256, 256>>>();
    k_hist<<<(E + 255) / 256, 256>>>(dst);
    k_scan1<<<SCAN_BLOCKS, 1024>>>();
    k_scan2<<<1, 32>>>();
    k_scan3<<<SCAN_BLOCKS, 1024>>>();
    k_scatter<<<(E + 255) / 256, 256>>>(dst, src);

    cudaStreamWaitEvent(0, ev_pre, 0);
    cudaStreamWaitEvent(0, ev_edge, 0);
    k_agg<<<(N * 32 + 255) / 256, 256>>>();
    k_nodegemm<<<(N + 127) / 128, 256>>>(h, p, snorm, Woh, boh, Wop, bop, out);
    k_bnapply<<<(N * 16 + 255) / 256, 256>>>(out, gamma, beta);
}

// round 15
// speedup vs baseline: 1.0613x; 1.0613x over previous
#include <cuda_runtime.h>
#include <cuda_fp16.h>
#include <math.h>

namespace {

constexpr int N = 50000;
constexpr int E = 800000;
constexpr float AVG_D_LOG = 2.8332f;
constexpr float EPS_STD = 1e-5f;
constexpr float EPS_BN = 1e-5f;
constexpr float FLT_BIG = 3.402823466e+38f;
constexpr int SCAN_BLOCKS = (N + 1023) / 1024;   // 49

typedef unsigned long long ull;

__device__ __forceinline__ float4 ldh4(const __half* ptr) {
    uint2 u = *(const uint2*)ptr;
    __half2 lo = *reinterpret_cast<__half2*>(&u.x);
    __half2 hi = *reinterpret_cast<__half2*>(&u.y);
    float2 f01 = __half22float2(lo), f23 = __half22float2(hi);
    return make_float4(f01.x, f01.y, f23.x, f23.y);
}
__device__ __forceinline__ uint4 ldsm_x4(unsigned addr) {
    uint4 r;
    asm volatile("ldmatrix.sync.aligned.m8n8.x4.shared.b16 {%0,%1,%2,%3}, [%4];"
                 : "=r"(r.x), "=r"(r.y), "=r"(r.z), "=r"(r.w) : "r"(addr));
    return r;
}
__device__ __forceinline__ uint4 ldsm_x4_t(unsigned addr) {
    uint4 r;
    asm volatile("ldmatrix.sync.aligned.m8n8.x4.trans.shared.b16 {%0,%1,%2,%3}, [%4];"
                 : "=r"(r.x), "=r"(r.y), "=r"(r.z), "=r"(r.w) : "r"(addr));
    return r;
}
__device__ __forceinline__ void mma16816(float* d, uint4 a, unsigned b0, unsigned b1) {
    asm volatile(
        "mma.sync.aligned.m16n8k16.row.col.f32.f16.f16.f32 "
        "{%0,%1,%2,%3},{%4,%5,%6,%7},{%8,%9},{%0,%1,%2,%3};"
        : "+f"(d[0]), "+f"(d[1]), "+f"(d[2]), "+f"(d[3])
        : "r"(a.x), "r"(a.y), "r"(a.z), "r"(a.w), "r"(b0), "r"(b1));
}

// ---- scratch (device globals: allocation-free contract) ----
__device__ int g_deg[N];
__device__ int g_offs[N + 1];
__device__ int g_cursor[N];
__device__ __align__(16) int2 g_sp[E];                   // (src, eid) at sorted pos
__device__ int g_btot[SCAN_BLOCKS];
__device__ int g_boff[SCAN_BLOCKS];
__device__ __align__(16) __half g_A[(size_t)N * 128];
__device__ __align__(16) __half g_B[(size_t)N * 128];
__device__ __align__(16) __half g_ce[(size_t)E * 128];   // ORIGINAL edge order
__device__ __align__(16) __half g_aggh[(size_t)N * 256]; // fp16 [mean|max|min|std]
__device__ __align__(16) __half g_aggp[(size_t)N * 256];
__device__ float g_amp[N];
__device__ float g_att[N];
__device__ float g_bnsum[64];
__device__ float g_bnsq[64];

// ---------------- init ----------------
__global__ void k_init() {
    int i = blockIdx.x * blockDim.x + threadIdx.x;
    if (i < N) g_deg[i] = 0;
    if (i < 64) { g_bnsum[i] = 0.f; g_bnsq[i] = 0.f; }
}

// ---------------- degree histogram ----------------
__global__ void k_hist(const int* __restrict__ dst) {
    int e = blockIdx.x * blockDim.x + threadIdx.x;
    if (e < E) atomicAdd(&g_deg[dst[e]], 1);
}

// ---------------- multi-block exclusive scan ----------------
__global__ void k_scan1() {
    __shared__ int ws[32];
    int t = threadIdx.x;
    int lane = t & 31, w = t >> 5;
    int base = blockIdx.x * 1024;
    int v = (base + t < N) ? g_deg[base + t] : 0;
    int x = v;
#pragma unroll
    for (int off = 1; off < 32; off <<= 1) {
        int y = __shfl_up_sync(0xffffffffu, x, off);
        if (lane >= off) x += y;
    }
    if (lane == 31) ws[w] = x;
    __syncthreads();
    if (w == 0) {
        int s = ws[lane];
#pragma unroll
        for (int off = 1; off < 32; off <<= 1) {
            int y = __shfl_up_sync(0xffffffffu, s, off);
            if (lane >= off) s += y;
        }
        ws[lane] = s;
    }
    __syncthreads();
    int incl = x + (w > 0 ? ws[w - 1] : 0);
    if (base + t < N) g_offs[base + t] = incl - v;
    if (t == 1023) g_btot[blockIdx.x] = incl;
}

__global__ void k_scan2() {
    if (threadIdx.x == 0) {
        int acc = 0;
        for (int i = 0; i < SCAN_BLOCKS; i++) {
            g_boff[i] = acc;
            acc += g_btot[i];
        }
    }
}

__global__ void k_scan3() {
    int t = threadIdx.x;
    int base = blockIdx.x * 1024;
    int off = g_boff[blockIdx.x];
    if (base + t < N) {
        int v = g_offs[base + t] + off;
        g_offs[base + t] = v;
        g_cursor[base + t] = v;
    }
    if (blockIdx.x == 0 && t == 0) g_offs[N] = E;
}

// ---------------- scatter: counting sort by dst, packed (src,eid) ----------------
__global__ void k_scatter(const int* __restrict__ dst, const int* __restrict__ src) {
    int e = blockIdx.x * blockDim.x + threadIdx.x;
    if (e < E) {
        int pos = atomicAdd(&g_cursor[dst[e]], 1);
        g_sp[pos] = make_int2(src[e], e);
    }
}

// ---------------- node pre-GEMMs via mma.sync -> fp16 g_A, g_B -------------------
constexpr int XP3 = 40;
constexpr int WP3 = 136;

__global__ void __launch_bounds__(256) k_nodepre(
    const float* __restrict__ h, const float* __restrict__ p,
    const float* __restrict__ Wh, const float* __restrict__ Wp)
{
    __shared__ __align__(16) __half Xs[128 * XP3];
    __shared__ __align__(16) __half Ws[32 * WP3];

    int tid = threadIdx.x;
    int base = blockIdx.x * 128;
    int w = tid >> 5;
    int l = tid & 31;
    int slab = w * 16;
    int r8 = l & 7;
    int mat = l >> 3;

    unsigned xsb = (unsigned)__cvta_generic_to_shared(Xs);
    unsigned wsb = (unsigned)__cvta_generic_to_shared(Ws);

    int xrow = tid >> 1;
    int xc0 = (tid & 1) * 16;
    int wk = tid >> 3;
    int wc0 = (tid & 7) * 16;

    float acc[16][4];

    // =========== phase h: K=128 ===========
#pragma unroll
    for (int j = 0; j < 16; j++)
#pragma unroll
        for (int q = 0; q < 4; q++) acc[j][q] = 0.f;

    for (int t = 0; t < 4; t++) {
        int k0 = t * 32;
        if (t) __syncthreads();
        {
            int n0 = base + xrow;
            __half* xd = Xs + xrow * XP3 + xc0;
            if (n0 < N) {
                const float* rp = h + (size_t)n0 * 128 + k0 + xc0;
#pragma unroll
                for (int q = 0; q < 4; q++) {
                    float4 a = *(const float4*)(rp + q * 4);
                    *(__half2*)(xd + q * 4)     = __floats2half2_rn(a.x, a.y);
                    *(__half2*)(xd + q * 4 + 2) = __floats2half2_rn(a.z, a.w);
                }
            } else {
                uint4 z = make_uint4(0, 0, 0, 0);
                *(uint4*)xd = z; *(uint4*)(xd + 8) = z;
            }
        }
        {
            const float* wr = (wc0 < 64) ? (Wh + (size_t)(k0 + wk) * 64 + wc0)
                                         : (Wh + (size_t)(128 + k0 + wk) * 64 + (wc0 - 64));
            __half* wd = Ws + wk * WP3 + wc0;
#pragma unroll
            for (int q = 0; q < 4; q++) {
                float4 a = *(const float4*)(wr + q * 4);
                *(__half2*)(wd + q * 4)     = __floats2half2_rn(a.x, a.y);
                *(__half2*)(wd + q * 4 + 2) = __floats2half2_rn(a.z, a.w);
            }
        }
        __syncthreads();
#pragma unroll
        for (int kc = 0; kc < 2; kc++) {
            int arow = slab + r8 + ((mat & 1) ? 8 : 0);
            int acol = kc * 16 + ((mat & 2) ? 8 : 0);
            uint4 a = ldsm_x4(xsb + (unsigned)(arow * XP3 + acol) * 2u);
            int bk = kc * 16 + r8 + ((mat & 1) ? 8 : 0);
#pragma unroll
            for (int j = 0; j < 8; j++) {
                int bn = j * 16 + ((mat & 2) ? 8 : 0);
                uint4 b = ldsm_x4_t(wsb + (unsigned)(bk * WP3 + bn) * 2u);
                mma16816(acc[2 * j],     a, b.x, b.y);
                mma16816(acc[2 * j + 1], a, b.z, b.w);
            }
        }
    }
    {
        int r0 = slab + (l >> 2);
        int c0 = (l & 3) * 2;
        int n0 = base + r0, n1 = base + r0 + 8;
        bool v0 = n0 < N, v1 = n1 < N;
#pragma unroll
        for (int j = 0; j < 16; j++) {
            int col = 8 * j + c0;
            __half* d0;
            __half* d1;
            if (col < 64) {
                d0 = g_A + (size_t)n0 * 128 + col;
                d1 = g_A + (size_t)n1 * 128 + col;
            } else {
                d0 = g_B + (size_t)n0 * 128 + (col - 64);
                d1 = g_B + (size_t)n1 * 128 + (col - 64);
            }
            if (v0) *(__half2*)d0 = __floats2half2_rn(acc[j][0], acc[j][1]);
            if (v1) *(__half2*)d1 = __floats2half2_rn(acc[j][2], acc[j][3]);
        }
    }

    // =========== phase p: K=64 ===========
#pragma unroll
    for (int j = 0; j < 16; j++)
#pragma unroll
        for (int q = 0; q < 4; q++) acc[j][q] = 0.f;

    for (int t = 0; t < 2; t++) {
        int k0 = t * 32;
        __syncthreads();
        {
            int n0 = base + xrow;
            __half* xd = Xs + xrow * XP3 + xc0;
            if (n0 < N) {
                const float* rp = p + (size_t)n0 * 64 + k0 + xc0;
#pragma unroll
                for (int q = 0; q < 4; q++) {
                    float4 a = *(const float4*)(rp + q * 4);
                    *(__half2*)(xd + q * 4)     = __floats2half2_rn(a.x, a.y);
                    *(__half2*)(xd + q * 4 + 2) = __floats2half2_rn(a.z, a.w);
                }
            } else {
                uint4 z = make_uint4(0, 0, 0, 0);
                *(uint4*)xd = z; *(uint4*)(xd + 8) = z;
            }
        }
        {
            const float* wr = (wc0 < 64) ? (Wp + (size_t)(k0 + wk) * 64 + wc0)
                                         : (Wp + (size_t)(64 + k0 + wk) * 64 + (wc0 - 64));
            __half* wd = Ws + wk * WP3 + wc0;
#pragma unroll
            for (int q = 0; q < 4; q++) {
                float4 a = *(const float4*)(wr + q * 4);
                *(__half2*)(wd + q * 4)     = __floats2half2_rn(a.x, a.y);
                *(__half2*)(wd + q * 4 + 2) = __floats2half2_rn(a.z, a.w);
            }
        }
        __syncthreads();
#pragma unroll
        for (int kc = 0; kc < 2; kc++) {
            int arow = slab + r8 + ((mat & 1) ? 8 : 0);
            int acol = kc * 16 + ((mat & 2) ? 8 : 0);
            uint4 a = ldsm_x4(xsb + (unsigned)(arow * XP3 + acol) * 2u);
            int bk = kc * 16 + r8 + ((mat & 1) ? 8 : 0);
#pragma unroll
            for (int j = 0; j < 8; j++) {
                int bn = j * 16 + ((mat & 2) ? 8 : 0);
                uint4 b = ldsm_x4_t(wsb + (unsigned)(bk * WP3 + bn) * 2u);
                mma16816(acc[2 * j],     a, b.x, b.y);
                mma16816(acc[2 * j + 1], a, b.z, b.w);
            }
        }
    }
    {
        int r0 = slab + (l >> 2);
        int c0 = (l & 3) * 2;
        int n0 = base + r0, n1 = base + r0 + 8;
        bool v0 = n0 < N, v1 = n1 < N;
#pragma unroll
        for (int j = 0; j < 16; j++) {
            int col = 8 * j + c0;
            __half* d0;
            __half* d1;
            if (col < 64) {
                d0 = g_A + (size_t)n0 * 128 + 64 + col;
                d1 = g_A + (size_t)n1 * 128 + 64 + col;
            } else {
                d0 = g_B + (size_t)n0 * 128 + col;
                d1 = g_B + (size_t)n1 * 128 + col;
            }
            if (v0) *(__half2*)d0 = __floats2half2_rn(acc[j][0], acc[j][1]);
            if (v1) *(__half2*)d1 = __floats2half2_rn(acc[j][2], acc[j][3]);
        }
    }
}

// ---------------- edge-feature GEMM via mma.sync (tensor cores) ------------------
constexpr int XP = 40;
constexpr int WP = 136;

__global__ void __launch_bounds__(256) k_edgeE(
    const float* __restrict__ ef,
    const float* __restrict__ Wh, const float* __restrict__ bh,
    const float* __restrict__ Wp, const float* __restrict__ bp)
{
    __shared__ __align__(16) __half Xs[128 * XP];
    __shared__ __align__(16) __half Ws[32 * WP];
    __shared__ float bias[128];

    int tid = threadIdx.x;
    int base = blockIdx.x * 128;
    int w = tid >> 5;
    int l = tid & 31;

    {
        int row = tid >> 1;
        int c0 = (tid & 1) * 16;
        const float* rowp = ef + (size_t)(base + row) * 32 + c0;
        __half* xd = Xs + row * XP + c0;
#pragma unroll
        for (int q = 0; q < 4; q++) {
            float4 a = *(const float4*)(rowp + q * 4);
            *(__half2*)(xd + q * 4)     = __floats2half2_rn(a.x, a.y);
            *(__half2*)(xd + q * 4 + 2) = __floats2half2_rn(a.z, a.w);
        }
    }
    {
        int k = tid >> 3;
        int c0 = (tid & 7) * 16;
        const float* wr = (c0 < 64) ? (Wh + (size_t)(256 + k) * 64 + c0)
                                    : (Wp + (size_t)(128 + k) * 64 + (c0 - 64));
        __half* wd = Ws + k * WP + c0;
#pragma unroll
        for (int q = 0; q < 4; q++) {
            float4 a = *(const float4*)(wr + q * 4);
            *(__half2*)(wd + q * 4)     = __floats2half2_rn(a.x, a.y);
            *(__half2*)(wd + q * 4 + 2) = __floats2half2_rn(a.z, a.w);
        }
    }
    if (tid < 128) bias[tid] = (tid < 64) ? bh[tid] : bp[tid - 64];
    __syncthreads();

    float acc[16][4];
#pragma unroll
    for (int j = 0; j < 16; j++)
#pragma unroll
        for (int q = 0; q < 4; q++) acc[j][q] = 0.f;

    int slab = w * 16;
    int r8 = l & 7;
    int mat = l >> 3;

    unsigned xsbase = (unsigned)__cvta_generic_to_shared(Xs);
    unsigned wsbase = (unsigned)__cvta_generic_to_shared(Ws);

#pragma unroll
    for (int kc = 0; kc < 2; kc++) {
        int arow = slab + r8 + ((mat & 1) ? 8 : 0);
        int acol = kc * 16 + ((mat & 2) ? 8 : 0);
        uint4 a = ldsm_x4(xsbase + (unsigned)(arow * XP + acol) * 2u);
#pragma unroll
        for (int j = 0; j < 8; j++) {
            int bk = kc * 16 + r8 + ((mat & 1) ? 8 : 0);
            int bn = j * 16 + ((mat & 2) ? 8 : 0);
            uint4 b = ldsm_x4_t(wsbase + (unsigned)(bk * WP + bn) * 2u);
            mma16816(acc[2 * j],     a, b.x, b.y);
            mma16816(acc[2 * j + 1], a, b.z, b.w);
        }
    }

    int r0 = slab + (l >> 2);
    int c0 = (l & 3) * 2;
    __half* out0 = g_ce + (size_t)(base + r0) * 128;
    __half* out1 = g_ce + (size_t)(base + r0 + 8) * 128;
#pragma unroll
    for (int j = 0; j < 16; j++) {
        int col = 8 * j + c0;
        float bz0 = bias[col], bz1 = bias[col + 1];
        *(__half2*)(out0 + col) = __floats2half2_rn(acc[j][0] + bz0, acc[j][1] + bz1);
        *(__half2*)(out1 + col) = __floats2half2_rn(acc[j][2] + bz0, acc[j][3] + bz1);
    }
}

// ---------------- fused message + PNA aggregation (round-13 layout + int2 sp) ----
// Lane l owns 4 CONSECUTIVE features: halfs [4l, 4l+4). Whole warp on one edge.
__global__ void k_agg() {
    int warp = (blockIdx.x * blockDim.x + threadIdx.x) >> 5;
    int l = threadIdx.x & 31;
    if (warp >= N) return;
    int n = warp;
    int s0 = g_offs[n];
    int s1 = g_offs[n + 1];
    int d = s1 - s0;

    int off4 = 4 * l;
    float4 bv = ldh4(g_B + (size_t)n * 128 + off4);

    float4 sm = make_float4(0.f, 0.f, 0.f, 0.f);
    float4 sq = make_float4(0.f, 0.f, 0.f, 0.f);
    float4 mx = make_float4(-FLT_BIG, -FLT_BIG, -FLT_BIG, -FLT_BIG);
    float4 mn = make_float4(FLT_BIG, FLT_BIG, FLT_BIG, FLT_BIG);

#define AGG_ACC(CV, AV)                                                          \
    do {                                                                         \
        float v0 = (CV).x + (AV).x + bv.x;                                       \
        float v1 = (CV).y + (AV).y + bv.y;                                       \
        float v2 = (CV).z + (AV).z + bv.z;                                       \
        float v3 = (CV).w + (AV).w + bv.w;                                       \
        sm.x += v0; sq.x += v0 * v0; mx.x = fmaxf(mx.x, v0); mn.x = fminf(mn.x, v0); \
        sm.y += v1; sq.y += v1 * v1; mx.y = fmaxf(mx.y, v1); mn.y = fminf(mn.y, v1); \
        sm.z += v2; sq.z += v2 * v2; mx.z = fmaxf(mx.z, v2); mn.z = fminf(mn.z, v2); \
        sm.w += v3; sq.w += v3 * v3; mx.w = fmaxf(mx.w, v3); mn.w = fminf(mn.w, v3); \
    } while (0)

    int i = s0;
    if ((s1 - s0) & 1) {
        int2 sp = g_sp[i];
        float4 cv = ldh4(g_ce + (size_t)sp.y * 128 + off4);
        float4 av = ldh4(g_A + (size_t)sp.x * 128 + off4);
        AGG_ACC(cv, av);
        i++;
    }
    for (; i < s1; i += 2) {
        int2 spA = g_sp[i];
        int2 spB = g_sp[i + 1];
        uint2 uCA = *(const uint2*)(g_ce + (size_t)spA.y * 128 + off4);
        uint2 uAA = *(const uint2*)(g_A + (size_t)spA.x * 128 + off4);
        uint2 uCB = *(const uint2*)(g_ce + (size_t)spB.y * 128 + off4);
        uint2 uAB = *(const uint2*)(g_A + (size_t)spB.x * 128 + off4);
        {
            __half2 lo = *reinterpret_cast<__half2*>(&uCA.x);
            __half2 hi = *reinterpret_cast<__half2*>(&uCA.y);
            float2 c01 = __half22float2(lo), c23 = __half22float2(hi);
            lo = *reinterpret_cast<__half2*>(&uAA.x);
            hi = *reinterpret_cast<__half2*>(&uAA.y);
            float2 a01 = __half22float2(lo), a23 = __half22float2(hi);
            float4 cv = make_float4(c01.x, c01.y, c23.x, c23.y);
            float4 av = make_float4(a01.x, a01.y, a23.x, a23.y);
            AGG_ACC(cv, av);
        }
        {
            __half2 lo = *reinterpret_cast<__half2*>(&uCB.x);
            __half2 hi = *reinterpret_cast<__half2*>(&uCB.y);
            float2 c01 = __half22float2(lo), c23 = __half22float2(hi);
            lo = *reinterpret_cast<__half2*>(&uAB.x);
            hi = *reinterpret_cast<__half2*>(&uAB.y);
            float2 a01 = __half22float2(lo), a23 = __half22float2(hi);
            float4 cv = make_float4(c01.x, c01.y, c23.x, c23.y);
            float4 av = make_float4(a01.x, a01.y, a23.x, a23.y);
            AGG_ACC(cv, av);
        }
    }
#undef AGG_ACC

    float degc = fmaxf((float)d, 1.f);
    float inv = 1.f / degc;
    bool has = d > 0;
    float logd = has ? logf((float)d + 1.f) : 1.f;
    float amp = logd / AVG_D_LOG;
    float att = AVG_D_LOG / logd;
    if (l == 0) { g_amp[n] = amp; g_att[n] = att; }

    __half* o = (off4 < 64) ? (g_aggh + (size_t)n * 256) : (g_aggp + (size_t)n * 256);
    int f = off4 & 63;

    float4 mean = make_float4(sm.x * inv, sm.y * inv, sm.z * inv, sm.w * inv);
    float4 var = make_float4(fmaxf(sq.x * inv - mean.x * mean.x, 0.f),
                             fmaxf(sq.y * inv - mean.y * mean.y, 0.f),
                             fmaxf(sq.z * inv - mean.z * mean.z, 0.f),
                             fmaxf(sq.w * inv - mean.w * mean.w, 0.f));
    float4 sd = make_float4(sqrtf(var.x + EPS_STD), sqrtf(var.y + EPS_STD),
                            sqrtf(var.z + EPS_STD), sqrtf(var.w + EPS_STD));
    float4 MX = has ? mx : make_float4(0.f, 0.f, 0.f, 0.f);
    float4 MN = has ? mn : make_float4(0.f, 0.f, 0.f, 0.f);
    *(__half2*)(o + f)       = __floats2half2_rn(mean.x, mean.y);
    *(__half2*)(o + f + 2)   = __floats2half2_rn(mean.z, mean.w);
    *(__half2*)(o + 64 + f)     = __floats2half2_rn(MX.x, MX.y);
    *(__half2*)(o + 64 + f + 2) = __floats2half2_rn(MX.z, MX.w);
    *(__half2*)(o + 128 + f)     = __floats2half2_rn(MN.x, MN.y);
    *(__half2*)(o + 128 + f + 2) = __floats2half2_rn(MN.z, MN.w);
    *(__half2*)(o + 192 + f)     = __floats2half2_rn(sd.x, sd.y);
    *(__half2*)(o + 192 + f + 2) = __floats2half2_rn(sd.z, sd.w);
}

// ---------------- node GEMMs via mma.sync: 3 rails + fused BN stats -------------
constexpr int XP2 = 40;
constexpr int WP2 = 72;

__global__ void __launch_bounds__(256) k_nodegemm(
    const float* __restrict__ h, const float* __restrict__ p,
    const float* __restrict__ snorm,
    const float* __restrict__ Woh, const float* __restrict__ boh,
    const float* __restrict__ Wop, const float* __restrict__ bop,
    float* __restrict__ out)
{
    __shared__ __align__(16) __half Xs[128 * XP2];
    __shared__ __align__(16) __half Ws[3][32 * WP2];
    __shared__ float sbias[64];
    __shared__ float s_amp[128], s_att[128], s_sn[128];
    __shared__ float sbn[64], sbq[64];

    int tid = threadIdx.x;
    int base = blockIdx.x * 128;
    int w = tid >> 5;
    int l = tid & 31;
    int slab = w * 16;
    int r8 = l & 7;
    int mat = l >> 3;

    if (tid < 128) {
        int n0 = base + tid;
        bool ok = n0 < N;
        s_amp[tid] = ok ? g_amp[n0] : 0.f;
        s_att[tid] = ok ? g_att[n0] : 0.f;
        s_sn[tid]  = ok ? snorm[n0] : 0.f;
    }
    if (tid < 64) { sbn[tid] = 0.f; sbq[tid] = 0.f; sbias[tid] = boh[tid]; }

    unsigned xsb = (unsigned)__cvta_generic_to_shared(Xs);
    unsigned wsb0 = (unsigned)__cvta_generic_to_shared(&Ws[0][0]);
    unsigned wsb1 = (unsigned)__cvta_generic_to_shared(&Ws[1][0]);
    unsigned wsb2 = (unsigned)__cvta_generic_to_shared(&Ws[2][0]);

    float accI[8][4], accA[8][4], accT[8][4];

    int xrow = tid >> 1;
    int xc0 = (tid & 1) * 16;
    int wk = (tid * 8) >> 6;
    int wn = (tid * 8) & 63;

    // ================= phase H =================
#pragma unroll
    for (int j = 0; j < 8; j++)
#pragma unroll
        for (int q = 0; q < 4; q++) { accI[j][q] = 0.f; accA[j][q] = 0.f; accT[j][q] = 0.f; }

    for (int t = 0; t < 12; t++) {
        int k0 = t * 32;
        bool isAgg = (t >= 4);
        __syncthreads();
        {
            int n0 = base + xrow;
            __half* xd = Xs + xrow * XP2 + xc0;
            if (n0 < N) {
                if (!isAgg) {
                    const float* rp = h + (size_t)n0 * 128 + k0 + xc0;
#pragma unroll
                    for (int q = 0; q < 4; q++) {
                        float4 a = *(const float4*)(rp + q * 4);
                        *(__half2*)(xd + q * 4)     = __floats2half2_rn(a.x, a.y);
                        *(__half2*)(xd + q * 4 + 2) = __floats2half2_rn(a.z, a.w);
                    }
                } else {
                    const __half* rp = g_aggh + (size_t)n0 * 256 + (k0 - 128) + xc0;
                    *(uint4*)xd       = *(const uint4*)rp;
                    *(uint4*)(xd + 8) = *(const uint4*)(rp + 8);
                }
            } else {
                uint4 z = make_uint4(0, 0, 0, 0);
                *(uint4*)xd = z; *(uint4*)(xd + 8) = z;
            }
        }
        {
            if (isAgg) {
                int aggk = k0 - 128;
                const float* wI = Woh + (size_t)(128 + aggk + wk) * 64 + wn;
                const float* wA = Woh + (size_t)(384 + aggk + wk) * 64 + wn;
                const float* wT = Woh + (size_t)(640 + aggk + wk) * 64 + wn;
                __half* dI = &Ws[0][wk * WP2 + wn];
                __half* dA = &Ws[1][wk * WP2 + wn];
                __half* dT = &Ws[2][wk * WP2 + wn];
#pragma unroll
                for (int q = 0; q < 2; q++) {
                    float4 a = *(const float4*)(wI + q * 4);
                    *(__half2*)(dI + q * 4)     = __floats2half2_rn(a.x, a.y);
                    *(__half2*)(dI + q * 4 + 2) = __floats2half2_rn(a.z, a.w);
                    a = *(const float4*)(wA + q * 4);
                    *(__half2*)(dA + q * 4)     = __floats2half2_rn(a.x, a.y);
                    *(__half2*)(dA + q * 4 + 2) = __floats2half2_rn(a.z, a.w);
                    a = *(const float4*)(wT + q * 4);
                    *(__half2*)(dT + q * 4)     = __floats2half2_rn(a.x, a.y);
                    *(__half2*)(dT + q * 4 + 2) = __floats2half2_rn(a.z, a.w);
                }
            } else {
                const float* wI = Woh + (size_t)(k0 + wk) * 64 + wn;
                __half* dI = &Ws[0][wk * WP2 + wn];
#pragma unroll
                for (int q = 0; q < 2; q++) {
                    float4 a = *(const float4*)(wI + q * 4);
                    *(__half2*)(dI + q * 4)     = __floats2half2_rn(a.x, a.y);
                    *(__half2*)(dI + q * 4 + 2) = __floats2half2_rn(a.z, a.w);
                }
            }
        }
        __syncthreads();
#pragma unroll
        for (int kc = 0; kc < 2; kc++) {
            int arow = slab + r8 + ((mat & 1) ? 8 : 0);
            int acol = kc * 16 + ((mat & 2) ? 8 : 0);
            uint4 a = ldsm_x4(xsb + (unsigned)(arow * XP2 + acol) * 2u);
            int bk = kc * 16 + r8 + ((mat & 1) ? 8 : 0);
#pragma unroll
            for (int j = 0; j < 4; j++) {
                int bn = j * 16 + ((mat & 2) ? 8 : 0);
                unsigned boff = (unsigned)(bk * WP2 + bn) * 2u;
                uint4 bI = ldsm_x4_t(wsb0 + boff);
                mma16816(accI[2 * j],     a, bI.x, bI.y);
                mma16816(accI[2 * j + 1], a, bI.z, bI.w);
                if (isAgg) {
                    uint4 bA = ldsm_x4_t(wsb1 + boff);
                    mma16816(accA[2 * j],     a, bA.x, bA.y);
                    mma16816(accA[2 * j + 1], a, bA.z, bA.w);
                    uint4 bT = ldsm_x4_t(wsb2 + boff);
                    mma16816(accT[2 * j],     a, bT.x, bT.y);
                    mma16816(accT[2 * j + 1], a, bT.z, bT.w);
                }
            }
        }
    }
    {
        int r0 = slab + (l >> 2);
        int c0l = (l & 3) * 2;
        int n0 = base + r0, n1 = base + r0 + 8;
        bool v0 = n0 < N, v1 = n1 < N;
        float amp0 = s_amp[r0], att0 = s_att[r0], sn0 = s_sn[r0];
        float amp1 = s_amp[r0 + 8], att1 = s_att[r0 + 8], sn1 = s_sn[r0 + 8];
#pragma unroll
        for (int j = 0; j < 8; j++) {
            int col = 8 * j + c0l;
            float b0 = sbias[col], b1 = sbias[col + 1];
            float y00 = (accI[j][0] + amp0 * accA[j][0] + att0 * accT[j][0] + b0) * sn0;
            float y01 = (accI[j][1] + amp0 * accA[j][1] + att0 * accT[j][1] + b1) * sn0;
            float y10 = (accI[j][2] + amp1 * accA[j][2] + att1 * accT[j][2] + b0) * sn1;
            float y11 = (accI[j][3] + amp1 * accA[j][3] + att1 * accT[j][3] + b1) * sn1;
            float ss0 = 0.f, ss1 = 0.f, qq0 = 0.f, qq1 = 0.f;
            if (v0) {
                *(float2*)&out[(size_t)n0 * 64 + col] = make_float2(y00, y01);
                ss0 += y00; ss1 += y01; qq0 += y00 * y00; qq1 += y01 * y01;
            }
            if (v1) {
                *(float2*)&out[(size_t)n1 * 64 + col] = make_float2(y10, y11);
                ss0 += y10; ss1 += y11; qq0 += y10 * y10; qq1 += y11 * y11;
            }
            atomicAdd(&sbn[col], ss0); atomicAdd(&sbn[col + 1], ss1);
            atomicAdd(&sbq[col], qq0); atomicAdd(&sbq[col + 1], qq1);
        }
    }
    __syncthreads();
    if (tid < 64) {
        atomicAdd(&g_bnsum[tid], sbn[tid]);
        atomicAdd(&g_bnsq[tid], sbq[tid]);
        sbias[tid] = bop[tid];
    }

    // ================= phase P =================
#pragma unroll
    for (int j = 0; j < 8; j++)
#pragma unroll
        for (int q = 0; q < 4; q++) { accI[j][q] = 0.f; accA[j][q] = 0.f; accT[j][q] = 0.f; }

    for (int t = 0; t < 10; t++) {
        int k0 = t * 32;
        bool isAgg = (t >= 2);
        __syncthreads();
        {
            int n0 = base + xrow;
            __half* xd = Xs + xrow * XP2 + xc0;
            if (n0 < N) {
                if (!isAgg) {
                    const float* rp = p + (size_t)n0 * 64 + k0 + xc0;
#pragma unroll
                    for (int q = 0; q < 4; q++) {
                        float4 a = *(const float4*)(rp + q * 4);
                        *(__half2*)(xd + q * 4)     = __floats2half2_rn(a.x, a.y);
                        *(__half2*)(xd + q * 4 + 2) = __floats2half2_rn(a.z, a.w);
                    }
                } else {
                    const __half* rp = g_aggp + (size_t)n0 * 256 + (k0 - 64) + xc0;
                    *(uint4*)xd       = *(const uint4*)rp;
                    *(uint4*)(xd + 8) = *(const uint4*)(rp + 8);
                }
            } else {
                uint4 z = make_uint4(0, 0, 0, 0);
                *(uint4*)xd = z; *(uint4*)(xd + 8) = z;
            }
        }
        {
            if (isAgg) {
                int aggk = k0 - 64;
                const float* wI = Wop + (size_t)(64 + aggk + wk) * 64 + wn;
                const float* wA = Wop + (size_t)(320 + aggk + wk) * 64 + wn;
                const float* wT = Wop + (size_t)(576 + aggk + wk) * 64 + wn;
                __half* dI = &Ws[0][wk * WP2 + wn];
                __half* dA = &Ws[1][wk * WP2 + wn];
                __half* dT = &Ws[2][wk * WP2 + wn];
#pragma unroll
                for (int q = 0; q < 2; q++) {
                    float4 a = *(const float4*)(wI + q * 4);
                    *(__half2*)(dI + q * 4)     = __floats2half2_rn(a.x, a.y);
                    *(__half2*)(dI + q * 4 + 2) = __floats2half2_rn(a.z, a.w);
                    a = *(const float4*)(wA + q * 4);
                    *(__half2*)(dA + q * 4)     = __floats2half2_rn(a.x, a.y);
                    *(__half2*)(dA + q * 4 + 2) = __floats2half2_rn(a.z, a.w);
                    a = *(const float4*)(wT + q * 4);
                    *(__half2*)(dT + q * 4)     = __floats2half2_rn(a.x, a.y);
                    *(__half2*)(dT + q * 4 + 2) = __floats2half2_rn(a.z, a.w);
                }
            } else {
                const float* wI = Wop + (size_t)(k0 + wk) * 64 + wn;
                __half* dI = &Ws[0][wk * WP2 + wn];
#pragma unroll
                for (int q = 0; q < 2; q++) {
                    float4 a = *(const float4*)(wI + q * 4);
                    *(__half2*)(dI + q * 4)     = __floats2half2_rn(a.x, a.y);
                    *(__half2*)(dI + q * 4 + 2) = __floats2half2_rn(a.z, a.w);
                }
            }
        }
        __syncthreads();
#pragma unroll
        for (int kc = 0; kc < 2; kc++) {
            int arow = slab + r8 + ((mat & 1) ? 8 : 0);
            int acol = kc * 16 + ((mat & 2) ? 8 : 0);
            uint4 a = ldsm_x4(xsb + (unsigned)(arow * XP2 + acol) * 2u);
            int bk = kc * 16 + r8 + ((mat & 1) ? 8 : 0);
#pragma unroll
            for (int j = 0; j < 4; j++) {
                int bn = j * 16 + ((mat & 2) ? 8 : 0);
                unsigned boff = (unsigned)(bk * WP2 + bn) * 2u;
                uint4 bI = ldsm_x4_t(wsb0 + boff);
                mma16816(accI[2 * j],     a, bI.x, bI.y);
                mma16816(accI[2 * j + 1], a, bI.z, bI.w);
                if (isAgg) {
                    uint4 bA = ldsm_x4_t(wsb1 + boff);
                    mma16816(accA[2 * j],     a, bA.x, bA.y);
                    mma16816(accA[2 * j + 1], a, bA.z, bA.w);
                    uint4 bT = ldsm_x4_t(wsb2 + boff);
                    mma16816(accT[2 * j],     a, bT.x, bT.y);
                    mma16816(accT[2 * j + 1], a, bT.z, bT.w);
                }
            }
        }
    }
    {
        int r0 = slab + (l >> 2);
        int c0l = (l & 3) * 2;
        int n0 = base + r0, n1 = base + r0 + 8;
        float amp0 = s_amp[r0], att0 = s_att[r0];
        float amp1 = s_amp[r0 + 8], att1 = s_att[r0 + 8];
        float* outp = out + (size_t)N * 64;
#pragma unroll
        for (int j = 0; j < 8; j++) {
            int col = 8 * j + c0l;
            float b0 = sbias[col], b1 = sbias[col + 1];
            float y00 = accI[j][0] + amp0 * accA[j][0] + att0 * accT[j][0] + b0;
            float y01 = accI[j][1] + amp0 * accA[j][1] + att0 * accT[j][1] + b1;
            float y10 = accI[j][2] + amp1 * accA[j][2] + att1 * accT[j][2] + b0;
            float y11 = accI[j][3] + amp1 * accA[j][3] + att1 * accT[j][3] + b1;
            if (n0 < N) *(float2*)&outp[(size_t)n0 * 64 + col] = make_float2(y00, y01);
            if (n1 < N) *(float2*)&outp[(size_t)n1 * 64 + col] = make_float2(y10, y11);
        }
    }
}

// ---------------- batchnorm apply (float4 vectorized) ----------------
__global__ void k_bnapply(float* __restrict__ out,
                          const float* __restrict__ gamma,
                          const float* __restrict__ beta) {
    int i = blockIdx.x * blockDim.x + threadIdx.x;
    if (i >= N * 16) return;
    int f = (i & 15) * 4;
    const float invN = 1.f / (float)N;
    float4 su = *(const float4*)&g_bnsum[f];
    float4 qu = *(const float4*)&g_bnsq[f];
    float4 ga = *(const float4*)&gamma[f];
    float4 be = *(const float4*)&beta[f];
    float4 mu = make_float4(su.x * invN, su.y * invN, su.z * invN, su.w * invN);
    float4 rs = make_float4(
        rsqrtf(qu.x * invN - mu.x * mu.x + EPS_BN),
        rsqrtf(qu.y * invN - mu.y * mu.y + EPS_BN),
        rsqrtf(qu.z * invN - mu.z * mu.z + EPS_BN),
        rsqrtf(qu.w * invN - mu.w * mu.w + EPS_BN));
    float4 x = *(float4*)&out[(size_t)i * 4];
    x.x = (x.x - mu.x) * rs.x * ga.x + be.x;
    x.y = (x.y - mu.y) * rs.y * ga.y + be.y;
    x.z = (x.z - mu.z) * rs.z * ga.z + be.z;
    x.w = (x.w - mu.w) * rs.w * ga.w + be.w;
    *(float4*)&out[(size_t)i * 4] = x;
}

} // namespace

extern "C" void kernel_launch(void* const* d_in, const int* in_sizes, int n_in,
                              void* d_out, int out_size) {
    const float* h     = (const float*)d_in[0];
    const float* p     = (const float*)d_in[1];
    const float* e     = (const float*)d_in[2];
    const int*   src   = (const int*)d_in[3];
    const int*   dst   = (const int*)d_in[4];
    const float* snorm = (const float*)d_in[5];
    const float* Wph   = (const float*)d_in[6];
    const float* bph   = (const float*)d_in[7];
    const float* Wpp   = (const float*)d_in[8];
    const float* bpp   = (const float*)d_in[9];
    const float* Woh   = (const float*)d_in[10];
    const float* boh   = (const float*)d_in[11];
    const float* Wop   = (const float*)d_in[12];
    const float* bop   = (const float*)d_in[13];
    const float* gamma = (const float*)d_in[14];
    const float* beta  = (const float*)d_in[15];
    float* out = (float*)d_out;

    static cudaStream_t s_pre = nullptr, s_edge = nullptr;
    static cudaEvent_t ev_fork = nullptr, ev_pre = nullptr, ev_edge = nullptr;
    if (s_pre == nullptr) {
        cudaStreamCreateWithFlags(&s_pre, cudaStreamNonBlocking);
        cudaStreamCreateWithFlags(&s_edge, cudaStreamNonBlocking);
        cudaEventCreateWithFlags(&ev_fork, cudaEventDisableTiming);
        cudaEventCreateWithFlags(&ev_pre, cudaEventDisableTiming);
        cudaEventCreateWithFlags(&ev_edge, cudaEventDisableTiming);
    }

    cudaEventRecord(ev_fork, 0);
    cudaStreamWaitEvent(s_pre, ev_fork, 0);
    cudaStreamWaitEvent(s_edge, ev_fork, 0);

    k_nodepre<<<(N + 127) / 128, 256, 0, s_pre>>>(h, p, Wph, Wpp);
    cudaEventRecord(ev_pre, s_pre);

    k_edgeE<<<E / 128, 256, 0, s_edge>>>(e, Wph, bph, Wpp, bpp);
    cudaEventRecord(ev_edge, s_edge);

    k_init<<<(N + 255) / 256, 256>>>();
    k_hist<<<(E + 255) / 256, 256>>>(dst);
    k_scan1<<<SCAN_BLOCKS, 1024>>>();
    k_scan2<<<1, 32>>>();
    k_scan3<<<SCAN_BLOCKS, 1024>>>();
    k_scatter<<<(E + 255) / 256, 256>>>(dst, src);

    cudaStreamWaitEvent(0, ev_pre, 0);
    cudaStreamWaitEvent(0, ev_edge, 0);
    k_agg<<<(N * 32 + 255) / 256, 256>>>();
    k_nodegemm<<<(N + 127) / 128, 256>>>(h, p, snorm, Woh, boh, Wop, bop, out);
    k_bnapply<<<(N * 16 + 255) / 256, 256>>>(out, gamma, beta);
}

// round 16
// speedup vs baseline: 1.1031x; 1.0394x over previous
#include <cuda_runtime.h>
#include <cuda_fp16.h>
#include <math.h>

namespace {

constexpr int N = 50000;
constexpr int E = 800000;
constexpr float AVG_D_LOG = 2.8332f;
constexpr float EPS_STD = 1e-5f;
constexpr float EPS_BN = 1e-5f;
constexpr float FLT_BIG = 3.402823466e+38f;
constexpr int SCAN_BLOCKS = (N + 1023) / 1024;   // 49

typedef unsigned long long ull;

__device__ __forceinline__ float4 ldh4(const __half* ptr) {
    uint2 u = *(const uint2*)ptr;
    __half2 lo = *reinterpret_cast<__half2*>(&u.x);
    __half2 hi = *reinterpret_cast<__half2*>(&u.y);
    float2 f01 = __half22float2(lo), f23 = __half22float2(hi);
    return make_float4(f01.x, f01.y, f23.x, f23.y);
}
__device__ __forceinline__ uint4 ldsm_x4(unsigned addr) {
    uint4 r;
    asm volatile("ldmatrix.sync.aligned.m8n8.x4.shared.b16 {%0,%1,%2,%3}, [%4];"
                 : "=r"(r.x), "=r"(r.y), "=r"(r.z), "=r"(r.w) : "r"(addr));
    return r;
}
__device__ __forceinline__ uint4 ldsm_x4_t(unsigned addr) {
    uint4 r;
    asm volatile("ldmatrix.sync.aligned.m8n8.x4.trans.shared.b16 {%0,%1,%2,%3}, [%4];"
                 : "=r"(r.x), "=r"(r.y), "=r"(r.z), "=r"(r.w) : "r"(addr));
    return r;
}
__device__ __forceinline__ void mma16816(float* d, uint4 a, unsigned b0, unsigned b1) {
    asm volatile(
        "mma.sync.aligned.m16n8k16.row.col.f32.f16.f16.f32 "
        "{%0,%1,%2,%3},{%4,%5,%6,%7},{%8,%9},{%0,%1,%2,%3};"
        : "+f"(d[0]), "+f"(d[1]), "+f"(d[2]), "+f"(d[3])
        : "r"(a.x), "r"(a.y), "r"(a.z), "r"(a.w), "r"(b0), "r"(b1));
}

// ---- scratch (device globals: allocation-free contract) ----
__device__ int g_deg[N];
__device__ int g_offs[N + 1];
__device__ int g_cursor[N];
__device__ int g_perm[E];
__device__ int g_srcs[E];
__device__ int g_btot[SCAN_BLOCKS];
__device__ int g_boff[SCAN_BLOCKS];
__device__ __align__(16) __half g_A[(size_t)N * 128];
__device__ __align__(16) __half g_B[(size_t)N * 128];
__device__ __align__(16) __half g_ce[(size_t)E * 128];   // ORIGINAL edge order
__device__ __align__(16) __half g_aggh[(size_t)N * 256]; // fp16 [mean|max|min|std]
__device__ __align__(16) __half g_aggp[(size_t)N * 256];
__device__ float g_amp[N];
__device__ float g_att[N];
__device__ float g_bnsum[64];
__device__ float g_bnsq[64];

// ---------------- init ----------------
__global__ void k_init() {
    int i = blockIdx.x * blockDim.x + threadIdx.x;
    if (i < N) g_deg[i] = 0;
    if (i < 64) { g_bnsum[i] = 0.f; g_bnsq[i] = 0.f; }
}

// ---------------- degree histogram ----------------
__global__ void k_hist(const int* __restrict__ dst) {
    int e = blockIdx.x * blockDim.x + threadIdx.x;
    if (e < E) atomicAdd(&g_deg[dst[e]], 1);
}

// ---------------- multi-block exclusive scan ----------------
__global__ void k_scan1() {
    __shared__ int ws[32];
    int t = threadIdx.x;
    int lane = t & 31, w = t >> 5;
    int base = blockIdx.x * 1024;
    int v = (base + t < N) ? g_deg[base + t] : 0;
    int x = v;
#pragma unroll
    for (int off = 1; off < 32; off <<= 1) {
        int y = __shfl_up_sync(0xffffffffu, x, off);
        if (lane >= off) x += y;
    }
    if (lane == 31) ws[w] = x;
    __syncthreads();
    if (w == 0) {
        int s = ws[lane];
#pragma unroll
        for (int off = 1; off < 32; off <<= 1) {
            int y = __shfl_up_sync(0xffffffffu, s, off);
            if (lane >= off) s += y;
        }
        ws[lane] = s;
    }
    __syncthreads();
    int incl = x + (w > 0 ? ws[w - 1] : 0);
    if (base + t < N) g_offs[base + t] = incl - v;
    if (t == 1023) g_btot[blockIdx.x] = incl;
}

__global__ void k_scan2() {
    if (threadIdx.x == 0) {
        int acc = 0;
        for (int i = 0; i < SCAN_BLOCKS; i++) {
            g_boff[i] = acc;
            acc += g_btot[i];
        }
    }
}

__global__ void k_scan3() {
    int t = threadIdx.x;
    int base = blockIdx.x * 1024;
    int off = g_boff[blockIdx.x];
    if (base + t < N) {
        int v = g_offs[base + t] + off;
        g_offs[base + t] = v;
        g_cursor[base + t] = v;
    }
    if (blockIdx.x == 0 && t == 0) g_offs[N] = E;
}

// ---------------- scatter: counting sort by dst ----------------
__global__ void k_scatter(const int* __restrict__ dst, const int* __restrict__ src) {
    int e = blockIdx.x * blockDim.x + threadIdx.x;
    if (e < E) {
        int pos = atomicAdd(&g_cursor[dst[e]], 1);
        g_perm[pos] = e;
        g_srcs[pos] = src[e];
    }
}

// ---------------- node pre-GEMMs via mma.sync -> fp16 g_A, g_B -------------------
constexpr int XP3 = 40;
constexpr int WP3 = 136;

__global__ void __launch_bounds__(256) k_nodepre(
    const float* __restrict__ h, const float* __restrict__ p,
    const float* __restrict__ Wh, const float* __restrict__ Wp)
{
    __shared__ __align__(16) __half Xs[128 * XP3];
    __shared__ __align__(16) __half Ws[32 * WP3];

    int tid = threadIdx.x;
    int base = blockIdx.x * 128;
    int w = tid >> 5;
    int l = tid & 31;
    int slab = w * 16;
    int r8 = l & 7;
    int mat = l >> 3;

    unsigned xsb = (unsigned)__cvta_generic_to_shared(Xs);
    unsigned wsb = (unsigned)__cvta_generic_to_shared(Ws);

    int xrow = tid >> 1;
    int xc0 = (tid & 1) * 16;
    int wk = tid >> 3;
    int wc0 = (tid & 7) * 16;

    float acc[16][4];

    // =========== phase h: K=128 ===========
#pragma unroll
    for (int j = 0; j < 16; j++)
#pragma unroll
        for (int q = 0; q < 4; q++) acc[j][q] = 0.f;

    for (int t = 0; t < 4; t++) {
        int k0 = t * 32;
        if (t) __syncthreads();
        {
            int n0 = base + xrow;
            __half* xd = Xs + xrow * XP3 + xc0;
            if (n0 < N) {
                const float* rp = h + (size_t)n0 * 128 + k0 + xc0;
#pragma unroll
                for (int q = 0; q < 4; q++) {
                    float4 a = *(const float4*)(rp + q * 4);
                    *(__half2*)(xd + q * 4)     = __floats2half2_rn(a.x, a.y);
                    *(__half2*)(xd + q * 4 + 2) = __floats2half2_rn(a.z, a.w);
                }
            } else {
                uint4 z = make_uint4(0, 0, 0, 0);
                *(uint4*)xd = z; *(uint4*)(xd + 8) = z;
            }
        }
        {
            const float* wr = (wc0 < 64) ? (Wh + (size_t)(k0 + wk) * 64 + wc0)
                                         : (Wh + (size_t)(128 + k0 + wk) * 64 + (wc0 - 64));
            __half* wd = Ws + wk * WP3 + wc0;
#pragma unroll
            for (int q = 0; q < 4; q++) {
                float4 a = *(const float4*)(wr + q * 4);
                *(__half2*)(wd + q * 4)     = __floats2half2_rn(a.x, a.y);
                *(__half2*)(wd + q * 4 + 2) = __floats2half2_rn(a.z, a.w);
            }
        }
        __syncthreads();
#pragma unroll
        for (int kc = 0; kc < 2; kc++) {
            int arow = slab + r8 + ((mat & 1) ? 8 : 0);
            int acol = kc * 16 + ((mat & 2) ? 8 : 0);
            uint4 a = ldsm_x4(xsb + (unsigned)(arow * XP3 + acol) * 2u);
            int bk = kc * 16 + r8 + ((mat & 1) ? 8 : 0);
#pragma unroll
            for (int j = 0; j < 8; j++) {
                int bn = j * 16 + ((mat & 2) ? 8 : 0);
                uint4 b = ldsm_x4_t(wsb + (unsigned)(bk * WP3 + bn) * 2u);
                mma16816(acc[2 * j],     a, b.x, b.y);
                mma16816(acc[2 * j + 1], a, b.z, b.w);
            }
        }
    }
    {
        int r0 = slab + (l >> 2);
        int c0 = (l & 3) * 2;
        int n0 = base + r0, n1 = base + r0 + 8;
        bool v0 = n0 < N, v1 = n1 < N;
#pragma unroll
        for (int j = 0; j < 16; j++) {
            int col = 8 * j + c0;
            __half* d0;
            __half* d1;
            if (col < 64) {
                d0 = g_A + (size_t)n0 * 128 + col;
                d1 = g_A + (size_t)n1 * 128 + col;
            } else {
                d0 = g_B + (size_t)n0 * 128 + (col - 64);
                d1 = g_B + (size_t)n1 * 128 + (col - 64);
            }
            if (v0) *(__half2*)d0 = __floats2half2_rn(acc[j][0], acc[j][1]);
            if (v1) *(__half2*)d1 = __floats2half2_rn(acc[j][2], acc[j][3]);
        }
    }

    // =========== phase p: K=64 ===========
#pragma unroll
    for (int j = 0; j < 16; j++)
#pragma unroll
        for (int q = 0; q < 4; q++) acc[j][q] = 0.f;

    for (int t = 0; t < 2; t++) {
        int k0 = t * 32;
        __syncthreads();
        {
            int n0 = base + xrow;
            __half* xd = Xs + xrow * XP3 + xc0;
            if (n0 < N) {
                const float* rp = p + (size_t)n0 * 64 + k0 + xc0;
#pragma unroll
                for (int q = 0; q < 4; q++) {
                    float4 a = *(const float4*)(rp + q * 4);
                    *(__half2*)(xd + q * 4)     = __floats2half2_rn(a.x, a.y);
                    *(__half2*)(xd + q * 4 + 2) = __floats2half2_rn(a.z, a.w);
                }
            } else {
                uint4 z = make_uint4(0, 0, 0, 0);
                *(uint4*)xd = z; *(uint4*)(xd + 8) = z;
            }
        }
        {
            const float* wr = (wc0 < 64) ? (Wp + (size_t)(k0 + wk) * 64 + wc0)
                                         : (Wp + (size_t)(64 + k0 + wk) * 64 + (wc0 - 64));
            __half* wd = Ws + wk * WP3 + wc0;
#pragma unroll
            for (int q = 0; q < 4; q++) {
                float4 a = *(const float4*)(wr + q * 4);
                *(__half2*)(wd + q * 4)     = __floats2half2_rn(a.x, a.y);
                *(__half2*)(wd + q * 4 + 2) = __floats2half2_rn(a.z, a.w);
            }
        }
        __syncthreads();
#pragma unroll
        for (int kc = 0; kc < 2; kc++) {
            int arow = slab + r8 + ((mat & 1) ? 8 : 0);
            int acol = kc * 16 + ((mat & 2) ? 8 : 0);
            uint4 a = ldsm_x4(xsb + (unsigned)(arow * XP3 + acol) * 2u);
            int bk = kc * 16 + r8 + ((mat & 1) ? 8 : 0);
#pragma unroll
            for (int j = 0; j < 8; j++) {
                int bn = j * 16 + ((mat & 2) ? 8 : 0);
                uint4 b = ldsm_x4_t(wsb + (unsigned)(bk * WP3 + bn) * 2u);
                mma16816(acc[2 * j],     a, b.x, b.y);
                mma16816(acc[2 * j + 1], a, b.z, b.w);
            }
        }
    }
    {
        int r0 = slab + (l >> 2);
        int c0 = (l & 3) * 2;
        int n0 = base + r0, n1 = base + r0 + 8;
        bool v0 = n0 < N, v1 = n1 < N;
#pragma unroll
        for (int j = 0; j < 16; j++) {
            int col = 8 * j + c0;
            __half* d0;
            __half* d1;
            if (col < 64) {
                d0 = g_A + (size_t)n0 * 128 + 64 + col;
                d1 = g_A + (size_t)n1 * 128 + 64 + col;
            } else {
                d0 = g_B + (size_t)n0 * 128 + col;
                d1 = g_B + (size_t)n1 * 128 + col;
            }
            if (v0) *(__half2*)d0 = __floats2half2_rn(acc[j][0], acc[j][1]);
            if (v1) *(__half2*)d1 = __floats2half2_rn(acc[j][2], acc[j][3]);
        }
    }
}

// ---------------- edge-feature GEMM via mma.sync (tensor cores) ------------------
constexpr int XP = 40;
constexpr int WP = 136;

__global__ void __launch_bounds__(256) k_edgeE(
    const float* __restrict__ ef,
    const float* __restrict__ Wh, const float* __restrict__ bh,
    const float* __restrict__ Wp, const float* __restrict__ bp)
{
    __shared__ __align__(16) __half Xs[128 * XP];
    __shared__ __align__(16) __half Ws[32 * WP];
    __shared__ float bias[128];

    int tid = threadIdx.x;
    int base = blockIdx.x * 128;
    int w = tid >> 5;
    int l = tid & 31;

    {
        int row = tid >> 1;
        int c0 = (tid & 1) * 16;
        const float* rowp = ef + (size_t)(base + row) * 32 + c0;
        __half* xd = Xs + row * XP + c0;
#pragma unroll
        for (int q = 0; q < 4; q++) {
            float4 a = *(const float4*)(rowp + q * 4);
            *(__half2*)(xd + q * 4)     = __floats2half2_rn(a.x, a.y);
            *(__half2*)(xd + q * 4 + 2) = __floats2half2_rn(a.z, a.w);
        }
    }
    {
        int k = tid >> 3;
        int c0 = (tid & 7) * 16;
        const float* wr = (c0 < 64) ? (Wh + (size_t)(256 + k) * 64 + c0)
                                    : (Wp + (size_t)(128 + k) * 64 + (c0 - 64));
        __half* wd = Ws + k * WP + c0;
#pragma unroll
        for (int q = 0; q < 4; q++) {
            float4 a = *(const float4*)(wr + q * 4);
            *(__half2*)(wd + q * 4)     = __floats2half2_rn(a.x, a.y);
            *(__half2*)(wd + q * 4 + 2) = __floats2half2_rn(a.z, a.w);
        }
    }
    if (tid < 128) bias[tid] = (tid < 64) ? bh[tid] : bp[tid - 64];
    __syncthreads();

    float acc[16][4];
#pragma unroll
    for (int j = 0; j < 16; j++)
#pragma unroll
        for (int q = 0; q < 4; q++) acc[j][q] = 0.f;

    int slab = w * 16;
    int r8 = l & 7;
    int mat = l >> 3;

    unsigned xsbase = (unsigned)__cvta_generic_to_shared(Xs);
    unsigned wsbase = (unsigned)__cvta_generic_to_shared(Ws);

#pragma unroll
    for (int kc = 0; kc < 2; kc++) {
        int arow = slab + r8 + ((mat & 1) ? 8 : 0);
        int acol = kc * 16 + ((mat & 2) ? 8 : 0);
        uint4 a = ldsm_x4(xsbase + (unsigned)(arow * XP + acol) * 2u);
#pragma unroll
        for (int j = 0; j < 8; j++) {
            int bk = kc * 16 + r8 + ((mat & 1) ? 8 : 0);
            int bn = j * 16 + ((mat & 2) ? 8 : 0);
            uint4 b = ldsm_x4_t(wsbase + (unsigned)(bk * WP + bn) * 2u);
            mma16816(acc[2 * j],     a, b.x, b.y);
            mma16816(acc[2 * j + 1], a, b.z, b.w);
        }
    }

    int r0 = slab + (l >> 2);
    int c0 = (l & 3) * 2;
    __half* out0 = g_ce + (size_t)(base + r0) * 128;
    __half* out1 = g_ce + (size_t)(base + r0 + 8) * 128;
#pragma unroll
    for (int j = 0; j < 16; j++) {
        int col = 8 * j + c0;
        float bz0 = bias[col], bz1 = bias[col + 1];
        *(__half2*)(out0 + col) = __floats2half2_rn(acc[j][0] + bz0, acc[j][1] + bz1);
        *(__half2*)(out1 + col) = __floats2half2_rn(acc[j][2] + bz0, acc[j][3] + bz1);
    }
}

// ---------------- fused message + PNA aggregation ----------------
// Lane l owns 4 CONSECUTIVE features: halfs [4l, 4l+4). Whole warp on one edge.
__global__ void k_agg() {
    int warp = (blockIdx.x * blockDim.x + threadIdx.x) >> 5;
    int l = threadIdx.x & 31;
    if (warp >= N) return;
    int n = warp;
    int s0 = g_offs[n];
    int s1 = g_offs[n + 1];
    int d = s1 - s0;

    int off4 = 4 * l;
    float4 bv = ldh4(g_B + (size_t)n * 128 + off4);

    float4 sm = make_float4(0.f, 0.f, 0.f, 0.f);
    float4 sq = make_float4(0.f, 0.f, 0.f, 0.f);
    float4 mx = make_float4(-FLT_BIG, -FLT_BIG, -FLT_BIG, -FLT_BIG);
    float4 mn = make_float4(FLT_BIG, FLT_BIG, FLT_BIG, FLT_BIG);

#define AGG_ACC(CV, AV)                                                          \
    do {                                                                         \
        float v0 = (CV).x + (AV).x + bv.x;                                       \
        float v1 = (CV).y + (AV).y + bv.y;                                       \
        float v2 = (CV).z + (AV).z + bv.z;                                       \
        float v3 = (CV).w + (AV).w + bv.w;                                       \
        sm.x += v0; sq.x += v0 * v0; mx.x = fmaxf(mx.x, v0); mn.x = fminf(mn.x, v0); \
        sm.y += v1; sq.y += v1 * v1; mx.y = fmaxf(mx.y, v1); mn.y = fminf(mn.y, v1); \
        sm.z += v2; sq.z += v2 * v2; mx.z = fmaxf(mx.z, v2); mn.z = fminf(mn.z, v2); \
        sm.w += v3; sq.w += v3 * v3; mx.w = fmaxf(mx.w, v3); mn.w = fminf(mn.w, v3); \
    } while (0)

    int i = s0;
    if ((s1 - s0) & 1) {
        int s = g_srcs[i];
        int eid = g_perm[i];
        float4 cv = ldh4(g_ce + (size_t)eid * 128 + off4);
        float4 av = ldh4(g_A + (size_t)s * 128 + off4);
        AGG_ACC(cv, av);
        i++;
    }
    for (; i < s1; i += 2) {
        int sA = g_srcs[i],   sB = g_srcs[i + 1];
        int eA = g_perm[i],   eB = g_perm[i + 1];
        uint2 uCA = *(const uint2*)(g_ce + (size_t)eA * 128 + off4);
        uint2 uAA = *(const uint2*)(g_A + (size_t)sA * 128 + off4);
        uint2 uCB = *(const uint2*)(g_ce + (size_t)eB * 128 + off4);
        uint2 uAB = *(const uint2*)(g_A + (size_t)sB * 128 + off4);
        {
            __half2 lo = *reinterpret_cast<__half2*>(&uCA.x);
            __half2 hi = *reinterpret_cast<__half2*>(&uCA.y);
            float2 c01 = __half22float2(lo), c23 = __half22float2(hi);
            lo = *reinterpret_cast<__half2*>(&uAA.x);
            hi = *reinterpret_cast<__half2*>(&uAA.y);
            float2 a01 = __half22float2(lo), a23 = __half22float2(hi);
            float4 cv = make_float4(c01.x, c01.y, c23.x, c23.y);
            float4 av = make_float4(a01.x, a01.y, a23.x, a23.y);
            AGG_ACC(cv, av);
        }
        {
            __half2 lo = *reinterpret_cast<__half2*>(&uCB.x);
            __half2 hi = *reinterpret_cast<__half2*>(&uCB.y);
            float2 c01 = __half22float2(lo), c23 = __half22float2(hi);
            lo = *reinterpret_cast<__half2*>(&uAB.x);
            hi = *reinterpret_cast<__half2*>(&uAB.y);
            float2 a01 = __half22float2(lo), a23 = __half22float2(hi);
            float4 cv = make_float4(c01.x, c01.y, c23.x, c23.y);
            float4 av = make_float4(a01.x, a01.y, a23.x, a23.y);
            AGG_ACC(cv, av);
        }
    }
#undef AGG_ACC

    float degc = fmaxf((float)d, 1.f);
    float inv = 1.f / degc;
    bool has = d > 0;
    float logd = has ? logf((float)d + 1.f) : 1.f;
    float amp = logd / AVG_D_LOG;
    float att = AVG_D_LOG / logd;
    if (l == 0) { g_amp[n] = amp; g_att[n] = att; }

    __half* o = (off4 < 64) ? (g_aggh + (size_t)n * 256) : (g_aggp + (size_t)n * 256);
    int f = off4 & 63;

    float4 mean = make_float4(sm.x * inv, sm.y * inv, sm.z * inv, sm.w * inv);
    float4 var = make_float4(fmaxf(sq.x * inv - mean.x * mean.x, 0.f),
                             fmaxf(sq.y * inv - mean.y * mean.y, 0.f),
                             fmaxf(sq.z * inv - mean.z * mean.z, 0.f),
                             fmaxf(sq.w * inv - mean.w * mean.w, 0.f));
    float4 sd = make_float4(sqrtf(var.x + EPS_STD), sqrtf(var.y + EPS_STD),
                            sqrtf(var.z + EPS_STD), sqrtf(var.w + EPS_STD));
    float4 MX = has ? mx : make_float4(0.f, 0.f, 0.f, 0.f);
    float4 MN = has ? mn : make_float4(0.f, 0.f, 0.f, 0.f);
    *(__half2*)(o + f)       = __floats2half2_rn(mean.x, mean.y);
    *(__half2*)(o + f + 2)   = __floats2half2_rn(mean.z, mean.w);
    *(__half2*)(o + 64 + f)     = __floats2half2_rn(MX.x, MX.y);
    *(__half2*)(o + 64 + f + 2) = __floats2half2_rn(MX.z, MX.w);
    *(__half2*)(o + 128 + f)     = __floats2half2_rn(MN.x, MN.y);
    *(__half2*)(o + 128 + f + 2) = __floats2half2_rn(MN.z, MN.w);
    *(__half2*)(o + 192 + f)     = __floats2half2_rn(sd.x, sd.y);
    *(__half2*)(o + 192 + f + 2) = __floats2half2_rn(sd.z, sd.w);
}

// ---------------- node GEMMs via mma.sync: 3 rails + fused BN stats -------------
constexpr int XP2 = 40;
constexpr int WP2 = 72;

__global__ void __launch_bounds__(256) k_nodegemm(
    const float* __restrict__ h, const float* __restrict__ p,
    const float* __restrict__ snorm,
    const float* __restrict__ Woh, const float* __restrict__ boh,
    const float* __restrict__ Wop, const float* __restrict__ bop,
    float* __restrict__ out)
{
    __shared__ __align__(16) __half Xs[128 * XP2];
    __shared__ __align__(16) __half Ws[3][32 * WP2];
    __shared__ float sbias[64];
    __shared__ float s_amp[128], s_att[128], s_sn[128];
    __shared__ float sbn[64], sbq[64];

    int tid = threadIdx.x;
    int base = blockIdx.x * 128;
    int w = tid >> 5;
    int l = tid & 31;
    int slab = w * 16;
    int r8 = l & 7;
    int mat = l >> 3;

    if (tid < 128) {
        int n0 = base + tid;
        bool ok = n0 < N;
        s_amp[tid] = ok ? g_amp[n0] : 0.f;
        s_att[tid] = ok ? g_att[n0] : 0.f;
        s_sn[tid]  = ok ? snorm[n0] : 0.f;
    }
    if (tid < 64) { sbn[tid] = 0.f; sbq[tid] = 0.f; sbias[tid] = boh[tid]; }

    unsigned xsb = (unsigned)__cvta_generic_to_shared(Xs);
    unsigned wsb0 = (unsigned)__cvta_generic_to_shared(&Ws[0][0]);
    unsigned wsb1 = (unsigned)__cvta_generic_to_shared(&Ws[1][0]);
    unsigned wsb2 = (unsigned)__cvta_generic_to_shared(&Ws[2][0]);

    float accI[8][4], accA[8][4], accT[8][4];

    int xrow = tid >> 1;
    int xc0 = (tid & 1) * 16;
    int wk = (tid * 8) >> 6;
    int wn = (tid * 8) & 63;

    // ================= phase H =================
#pragma unroll
    for (int j = 0; j < 8; j++)
#pragma unroll
        for (int q = 0; q < 4; q++) { accI[j][q] = 0.f; accA[j][q] = 0.f; accT[j][q] = 0.f; }

    for (int t = 0; t < 12; t++) {
        int k0 = t * 32;
        bool isAgg = (t >= 4);
        __syncthreads();
        {
            int n0 = base + xrow;
            __half* xd = Xs + xrow * XP2 + xc0;
            if (n0 < N) {
                if (!isAgg) {
                    const float* rp = h + (size_t)n0 * 128 + k0 + xc0;
#pragma unroll
                    for (int q = 0; q < 4; q++) {
                        float4 a = *(const float4*)(rp + q * 4);
                        *(__half2*)(xd + q * 4)     = __floats2half2_rn(a.x, a.y);
                        *(__half2*)(xd + q * 4 + 2) = __floats2half2_rn(a.z, a.w);
                    }
                } else {
                    const __half* rp = g_aggh + (size_t)n0 * 256 + (k0 - 128) + xc0;
                    *(uint4*)xd       = *(const uint4*)rp;
                    *(uint4*)(xd + 8) = *(const uint4*)(rp + 8);
                }
            } else {
                uint4 z = make_uint4(0, 0, 0, 0);
                *(uint4*)xd = z; *(uint4*)(xd + 8) = z;
            }
        }
        {
            if (isAgg) {
                int aggk = k0 - 128;
                const float* wI = Woh + (size_t)(128 + aggk + wk) * 64 + wn;
                const float* wA = Woh + (size_t)(384 + aggk + wk) * 64 + wn;
                const float* wT = Woh + (size_t)(640 + aggk + wk) * 64 + wn;
                __half* dI = &Ws[0][wk * WP2 + wn];
                __half* dA = &Ws[1][wk * WP2 + wn];
                __half* dT = &Ws[2][wk * WP2 + wn];
#pragma unroll
                for (int q = 0; q < 2; q++) {
                    float4 a = *(const float4*)(wI + q * 4);
                    *(__half2*)(dI + q * 4)     = __floats2half2_rn(a.x, a.y);
                    *(__half2*)(dI + q * 4 + 2) = __floats2half2_rn(a.z, a.w);
                    a = *(const float4*)(wA + q * 4);
                    *(__half2*)(dA + q * 4)     = __floats2half2_rn(a.x, a.y);
                    *(__half2*)(dA + q * 4 + 2) = __floats2half2_rn(a.z, a.w);
                    a = *(const float4*)(wT + q * 4);
                    *(__half2*)(dT + q * 4)     = __floats2half2_rn(a.x, a.y);
                    *(__half2*)(dT + q * 4 + 2) = __floats2half2_rn(a.z, a.w);
                }
            } else {
                const float* wI = Woh + (size_t)(k0 + wk) * 64 + wn;
                __half* dI = &Ws[0][wk * WP2 + wn];
#pragma unroll
                for (int q = 0; q < 2; q++) {
                    float4 a = *(const float4*)(wI + q * 4);
                    *(__half2*)(dI + q * 4)     = __floats2half2_rn(a.x, a.y);
                    *(__half2*)(dI + q * 4 + 2) = __floats2half2_rn(a.z, a.w);
                }
            }
        }
        __syncthreads();
#pragma unroll
        for (int kc = 0; kc < 2; kc++) {
            int arow = slab + r8 + ((mat & 1) ? 8 : 0);
            int acol = kc * 16 + ((mat & 2) ? 8 : 0);
            uint4 a = ldsm_x4(xsb + (unsigned)(arow * XP2 + acol) * 2u);
            int bk = kc * 16 + r8 + ((mat & 1) ? 8 : 0);
#pragma unroll
            for (int j = 0; j < 4; j++) {
                int bn = j * 16 + ((mat & 2) ? 8 : 0);
                unsigned boff = (unsigned)(bk * WP2 + bn) * 2u;
                uint4 bI = ldsm_x4_t(wsb0 + boff);
                mma16816(accI[2 * j],     a, bI.x, bI.y);
                mma16816(accI[2 * j + 1], a, bI.z, bI.w);
                if (isAgg) {
                    uint4 bA = ldsm_x4_t(wsb1 + boff);
                    mma16816(accA[2 * j],     a, bA.x, bA.y);
                    mma16816(accA[2 * j + 1], a, bA.z, bA.w);
                    uint4 bT = ldsm_x4_t(wsb2 + boff);
                    mma16816(accT[2 * j],     a, bT.x, bT.y);
                    mma16816(accT[2 * j + 1], a, bT.z, bT.w);
                }
            }
        }
    }
    {
        int r0 = slab + (l >> 2);
        int c0l = (l & 3) * 2;
        int n0 = base + r0, n1 = base + r0 + 8;
        bool v0 = n0 < N, v1 = n1 < N;
        float amp0 = s_amp[r0], att0 = s_att[r0], sn0 = s_sn[r0];
        float amp1 = s_amp[r0 + 8], att1 = s_att[r0 + 8], sn1 = s_sn[r0 + 8];
#pragma unroll
        for (int j = 0; j < 8; j++) {
            int col = 8 * j + c0l;
            float b0 = sbias[col], b1 = sbias[col + 1];
            float y00 = (accI[j][0] + amp0 * accA[j][0] + att0 * accT[j][0] + b0) * sn0;
            float y01 = (accI[j][1] + amp0 * accA[j][1] + att0 * accT[j][1] + b1) * sn0;
            float y10 = (accI[j][2] + amp1 * accA[j][2] + att1 * accT[j][2] + b0) * sn1;
            float y11 = (accI[j][3] + amp1 * accA[j][3] + att1 * accT[j][3] + b1) * sn1;
            float ss0 = 0.f, ss1 = 0.f, qq0 = 0.f, qq1 = 0.f;
            if (v0) {
                *(float2*)&out[(size_t)n0 * 64 + col] = make_float2(y00, y01);
                ss0 += y00; ss1 += y01; qq0 += y00 * y00; qq1 += y01 * y01;
            }
            if (v1) {
                *(float2*)&out[(size_t)n1 * 64 + col] = make_float2(y10, y11);
                ss0 += y10; ss1 += y11; qq0 += y10 * y10; qq1 += y11 * y11;
            }
            atomicAdd(&sbn[col], ss0); atomicAdd(&sbn[col + 1], ss1);
            atomicAdd(&sbq[col], qq0); atomicAdd(&sbq[col + 1], qq1);
        }
    }
    __syncthreads();
    if (tid < 64) {
        atomicAdd(&g_bnsum[tid], sbn[tid]);
        atomicAdd(&g_bnsq[tid], sbq[tid]);
        sbias[tid] = bop[tid];
    }

    // ================= phase P =================
#pragma unroll
    for (int j = 0; j < 8; j++)
#pragma unroll
        for (int q = 0; q < 4; q++) { accI[j][q] = 0.f; accA[j][q] = 0.f; accT[j][q] = 0.f; }

    for (int t = 0; t < 10; t++) {
        int k0 = t * 32;
        bool isAgg = (t >= 2);
        __syncthreads();
        {
            int n0 = base + xrow;
            __half* xd = Xs + xrow * XP2 + xc0;
            if (n0 < N) {
                if (!isAgg) {
                    const float* rp = p + (size_t)n0 * 64 + k0 + xc0;
#pragma unroll
                    for (int q = 0; q < 4; q++) {
                        float4 a = *(const float4*)(rp + q * 4);
                        *(__half2*)(xd + q * 4)     = __floats2half2_rn(a.x, a.y);
                        *(__half2*)(xd + q * 4 + 2) = __floats2half2_rn(a.z, a.w);
                    }
                } else {
                    const __half* rp = g_aggp + (size_t)n0 * 256 + (k0 - 64) + xc0;
                    *(uint4*)xd       = *(const uint4*)rp;
                    *(uint4*)(xd + 8) = *(const uint4*)(rp + 8);
                }
            } else {
                uint4 z = make_uint4(0, 0, 0, 0);
                *(uint4*)xd = z; *(uint4*)(xd + 8) = z;
            }
        }
        {
            if (isAgg) {
                int aggk = k0 - 64;
                const float* wI = Wop + (size_t)(64 + aggk + wk) * 64 + wn;
                const float* wA = Wop + (size_t)(320 + aggk + wk) * 64 + wn;
                const float* wT = Wop + (size_t)(576 + aggk + wk) * 64 + wn;
                __half* dI = &Ws[0][wk * WP2 + wn];
                __half* dA = &Ws[1][wk * WP2 + wn];
                __half* dT = &Ws[2][wk * WP2 + wn];
#pragma unroll
                for (int q = 0; q < 2; q++) {
                    float4 a = *(const float4*)(wI + q * 4);
                    *(__half2*)(dI + q * 4)     = __floats2half2_rn(a.x, a.y);
                    *(__half2*)(dI + q * 4 + 2) = __floats2half2_rn(a.z, a.w);
                    a = *(const float4*)(wA + q * 4);
                    *(__half2*)(dA + q * 4)     = __floats2half2_rn(a.x, a.y);
                    *(__half2*)(dA + q * 4 + 2) = __floats2half2_rn(a.z, a.w);
                    a = *(const float4*)(wT + q * 4);
                    *(__half2*)(dT + q * 4)     = __floats2half2_rn(a.x, a.y);
                    *(__half2*)(dT + q * 4 + 2) = __floats2half2_rn(a.z, a.w);
                }
            } else {
                const float* wI = Wop + (size_t)(k0 + wk) * 64 + wn;
                __half* dI = &Ws[0][wk * WP2 + wn];
#pragma unroll
                for (int q = 0; q < 2; q++) {
                    float4 a = *(const float4*)(wI + q * 4);
                    *(__half2*)(dI + q * 4)     = __floats2half2_rn(a.x, a.y);
                    *(__half2*)(dI + q * 4 + 2) = __floats2half2_rn(a.z, a.w);
                }
            }
        }
        __syncthreads();
#pragma unroll
        for (int kc = 0; kc < 2; kc++) {
            int arow = slab + r8 + ((mat & 1) ? 8 : 0);
            int acol = kc * 16 + ((mat & 2) ? 8 : 0);
            uint4 a = ldsm_x4(xsb + (unsigned)(arow * XP2 + acol) * 2u);
            int bk = kc * 16 + r8 + ((mat & 1) ? 8 : 0);
#pragma unroll
            for (int j = 0; j < 4; j++) {
                int bn = j * 16 + ((mat & 2) ? 8 : 0);
                unsigned boff = (unsigned)(bk * WP2 + bn) * 2u;
                uint4 bI = ldsm_x4_t(wsb0 + boff);
                mma16816(accI[2 * j],     a, bI.x, bI.y);
                mma16816(accI[2 * j + 1], a, bI.z, bI.w);
                if (isAgg) {
                    uint4 bA = ldsm_x4_t(wsb1 + boff);
                    mma16816(accA[2 * j],     a, bA.x, bA.y);
                    mma16816(accA[2 * j + 1], a, bA.z, bA.w);
                    uint4 bT = ldsm_x4_t(wsb2 + boff);
                    mma16816(accT[2 * j],     a, bT.x, bT.y);
                    mma16816(accT[2 * j + 1], a, bT.z, bT.w);
                }
            }
        }
    }
    {
        int r0 = slab + (l >> 2);
        int c0l = (l & 3) * 2;
        int n0 = base + r0, n1 = base + r0 + 8;
        float amp0 = s_amp[r0], att0 = s_att[r0];
        float amp1 = s_amp[r0 + 8], att1 = s_att[r0 + 8];
        float* outp = out + (size_t)N * 64;
#pragma unroll
        for (int j = 0; j < 8; j++) {
            int col = 8 * j + c0l;
            float b0 = sbias[col], b1 = sbias[col + 1];
            float y00 = accI[j][0] + amp0 * accA[j][0] + att0 * accT[j][0] + b0;
            float y01 = accI[j][1] + amp0 * accA[j][1] + att0 * accT[j][1] + b1;
            float y10 = accI[j][2] + amp1 * accA[j][2] + att1 * accT[j][2] + b0;
            float y11 = accI[j][3] + amp1 * accA[j][3] + att1 * accT[j][3] + b1;
            if (n0 < N) *(float2*)&out[(size_t)N * 64 + (size_t)n0 * 64 + col] = make_float2(y00, y01);
            if (n1 < N) *(float2*)&outp[(size_t)n1 * 64 + col] = make_float2(y10, y11);
        }
    }
}

// ---------------- batchnorm apply (float4 vectorized) ----------------
__global__ void k_bnapply(float* __restrict__ out,
                          const float* __restrict__ gamma,
                          const float* __restrict__ beta) {
    int i = blockIdx.x * blockDim.x + threadIdx.x;
    if (i >= N * 16) return;
    int f = (i & 15) * 4;
    const float invN = 1.f / (float)N;
    float4 su = *(const float4*)&g_bnsum[f];
    float4 qu = *(const float4*)&g_bnsq[f];
    float4 ga = *(const float4*)&gamma[f];
    float4 be = *(const float4*)&beta[f];
    float4 mu = make_float4(su.x * invN, su.y * invN, su.z * invN, su.w * invN);
    float4 rs = make_float4(
        rsqrtf(qu.x * invN - mu.x * mu.x + EPS_BN),
        rsqrtf(qu.y * invN - mu.y * mu.y + EPS_BN),
        rsqrtf(qu.z * invN - mu.z * mu.z + EPS_BN),
        rsqrtf(qu.w * invN - mu.w * mu.w + EPS_BN));
    float4 x = *(float4*)&out[(size_t)i * 4];
    x.x = (x.x - mu.x) * rs.x * ga.x + be.x;
    x.y = (x.y - mu.y) * rs.y * ga.y + be.y;
    x.z = (x.z - mu.z) * rs.z * ga.z + be.z;
    x.w = (x.w - mu.w) * rs.w * ga.w + be.w;
    *(float4*)&out[(size_t)i * 4] = x;
}

} // namespace

extern "C" void kernel_launch(void* const* d_in, const int* in_sizes, int n_in,
                              void* d_out, int out_size) {
    const float* h     = (const float*)d_in[0];
    const float* p     = (const float*)d_in[1];
    const float* e     = (const float*)d_in[2];
    const int*   src   = (const int*)d_in[3];
    const int*   dst   = (const int*)d_in[4];
    const float* snorm = (const float*)d_in[5];
    const float* Wph   = (const float*)d_in[6];
    const float* bph   = (const float*)d_in[7];
    const float* Wpp   = (const float*)d_in[8];
    const float* bpp   = (const float*)d_in[9];
    const float* Woh   = (const float*)d_in[10];
    const float* boh   = (const float*)d_in[11];
    const float* Wop   = (const float*)d_in[12];
    const float* bop   = (const float*)d_in[13];
    const float* gamma = (const float*)d_in[14];
    const float* beta  = (const float*)d_in[15];
    float* out = (float*)d_out;

    static cudaStream_t s_pre = nullptr, s_edge = nullptr;
    static cudaEvent_t ev_fork = nullptr, ev_pre = nullptr, ev_edge = nullptr;
    if (s_pre == nullptr) {
        cudaStreamCreateWithFlags(&s_pre, cudaStreamNonBlocking);
        cudaStreamCreateWithFlags(&s_edge, cudaStreamNonBlocking);
        cudaEventCreateWithFlags(&ev_fork, cudaEventDisableTiming);
        cudaEventCreateWithFlags(&ev_pre, cudaEventDisableTiming);
        cudaEventCreateWithFlags(&ev_edge, cudaEventDisableTiming);
    }

    cudaEventRecord(ev_fork, 0);
    cudaStreamWaitEvent(s_pre, ev_fork, 0);
    cudaStreamWaitEvent(s_edge, ev_fork, 0);

    k_nodepre<<<(N + 127) / 128, 256, 0, s_pre>>>(h, p, Wph, Wpp);
    cudaEventRecord(ev_pre, s_pre);

    k_edgeE<<<E / 128, 256, 0, s_edge>>>(e, Wph, bph, Wpp, bpp);
    cudaEventRecord(ev_edge, s_edge);

    k_init<<<(N + 255) / 256, 256>>>();
    k_hist<<<(E + 255) / 256, 256>>>(dst);
    k_scan1<<<SCAN_BLOCKS, 1024>>>();
    k_scan2<<<1, 32>>>();
    k_scan3<<<SCAN_BLOCKS, 1024>>>();
    k_scatter<<<(E + 255) / 256, 256>>>(dst, src);

    cudaStreamWaitEvent(0, ev_pre, 0);
    cudaStreamWaitEvent(0, ev_edge, 0);
    k_agg<<<(N * 32 + 255) / 256, 256>>>();
    k_nodegemm<<<(N + 127) / 128, 256>>>(h, p, snorm, Woh, boh, Wop, bop, out);
    k_bnapply<<<(N * 16 + 255) / 256, 256>>>(out, gamma, beta);
}

// round 17
// speedup vs baseline: 1.1904x; 1.0792x over previous
#include <cuda_runtime.h>
#include <cuda_fp16.h>
#include <math.h>

namespace {

constexpr int N = 50000;
constexpr int E = 800000;
constexpr float AVG_D_LOG = 2.8332f;
constexpr float EPS_STD = 1e-5f;
constexpr float EPS_BN = 1e-5f;
constexpr float FLT_BIG = 3.402823466e+38f;
constexpr int SCAN_BLOCKS = (N + 1023) / 1024;   // 49

typedef unsigned long long ull;

__device__ __forceinline__ float4 ldh4(const __half* ptr) {
    uint2 u = *(const uint2*)ptr;
    __half2 lo = *reinterpret_cast<__half2*>(&u.x);
    __half2 hi = *reinterpret_cast<__half2*>(&u.y);
    float2 f01 = __half22float2(lo), f23 = __half22float2(hi);
    return make_float4(f01.x, f01.y, f23.x, f23.y);
}
__device__ __forceinline__ uint4 ldsm_x4(unsigned addr) {
    uint4 r;
    asm volatile("ldmatrix.sync.aligned.m8n8.x4.shared.b16 {%0,%1,%2,%3}, [%4];"
                 : "=r"(r.x), "=r"(r.y), "=r"(r.z), "=r"(r.w) : "r"(addr));
    return r;
}
__device__ __forceinline__ uint4 ldsm_x4_t(unsigned addr) {
    uint4 r;
    asm volatile("ldmatrix.sync.aligned.m8n8.x4.trans.shared.b16 {%0,%1,%2,%3}, [%4];"
                 : "=r"(r.x), "=r"(r.y), "=r"(r.z), "=r"(r.w) : "r"(addr));
    return r;
}
__device__ __forceinline__ void mma16816(float* d, uint4 a, unsigned b0, unsigned b1) {
    asm volatile(
        "mma.sync.aligned.m16n8k16.row.col.f32.f16.f16.f32 "
        "{%0,%1,%2,%3},{%4,%5,%6,%7},{%8,%9},{%0,%1,%2,%3};"
        : "+f"(d[0]), "+f"(d[1]), "+f"(d[2]), "+f"(d[3])
        : "r"(a.x), "r"(a.y), "r"(a.z), "r"(a.w), "r"(b0), "r"(b1));
}

// ---- scratch (device globals: allocation-free contract) ----
__device__ int g_deg[N];
__device__ int g_offs[N + 1];
__device__ int g_cursor[N];
__device__ int g_perm[E];
__device__ int g_srcs[E];
__device__ int g_btot[SCAN_BLOCKS];
__device__ int g_boff[SCAN_BLOCKS];
__device__ __align__(16) __half g_A[(size_t)N * 128];
__device__ __align__(16) __half g_B[(size_t)N * 128];
__device__ __align__(16) __half g_ce[(size_t)E * 128];   // ORIGINAL edge order
__device__ __align__(16) __half g_aggh[(size_t)N * 256]; // fp16 [mean|max|min|std]
__device__ __align__(16) __half g_aggp[(size_t)N * 256];
__device__ float g_amp[N];
__device__ float g_att[N];
__device__ float g_bnsum[64];
__device__ float g_bnsq[64];
// fp16 pre-converted inputs
__device__ __align__(16) __half g_h16[(size_t)N * 128];
__device__ __align__(16) __half g_p16[(size_t)N * 64];
__device__ __align__(16) __half g_Wph16[288 * 64];
__device__ __align__(16) __half g_Wpp16[160 * 64];
__device__ __align__(16) __half g_Woh16[896 * 64];
__device__ __align__(16) __half g_Wop16[832 * 64];

// ---------------- fp16 pre-conversion ----------------
__global__ void k_cvt_feat(const float* __restrict__ h, const float* __restrict__ p) {
    const int NH4 = N * 128 / 4, NP4 = N * 64 / 4;
    for (int i = blockIdx.x * blockDim.x + threadIdx.x; i < NH4 + NP4;
         i += gridDim.x * blockDim.x) {
        if (i < NH4) {
            float4 a = *(const float4*)(h + (size_t)i * 4);
            __half2* d = (__half2*)(g_h16 + (size_t)i * 4);
            d[0] = __floats2half2_rn(a.x, a.y);
            d[1] = __floats2half2_rn(a.z, a.w);
        } else {
            int j = i - NH4;
            float4 a = *(const float4*)(p + (size_t)j * 4);
            __half2* d = (__half2*)(g_p16 + (size_t)j * 4);
            d[0] = __floats2half2_rn(a.x, a.y);
            d[1] = __floats2half2_rn(a.z, a.w);
        }
    }
}

__global__ void k_cvt_w(const float* __restrict__ Wph, const float* __restrict__ Wpp,
                        const float* __restrict__ Woh, const float* __restrict__ Wop) {
    const int S0 = 288 * 64 / 4, S1 = S0 + 160 * 64 / 4;
    const int S2 = S1 + 896 * 64 / 4, S3 = S2 + 832 * 64 / 4;
    for (int i = blockIdx.x * blockDim.x + threadIdx.x; i < S3;
         i += gridDim.x * blockDim.x) {
        const float* s;
        __half* d;
        int j;
        if (i < S0)      { j = i;      s = Wph; d = g_Wph16; }
        else if (i < S1) { j = i - S0; s = Wpp; d = g_Wpp16; }
        else if (i < S2) { j = i - S1; s = Woh; d = g_Woh16; }
        else             { j = i - S2; s = Wop; d = g_Wop16; }
        float4 a = *(const float4*)(s + (size_t)j * 4);
        __half2* dp = (__half2*)(d + (size_t)j * 4);
        dp[0] = __floats2half2_rn(a.x, a.y);
        dp[1] = __floats2half2_rn(a.z, a.w);
    }
}

// ---------------- init ----------------
__global__ void k_init() {
    int i = blockIdx.x * blockDim.x + threadIdx.x;
    if (i < N) g_deg[i] = 0;
    if (i < 64) { g_bnsum[i] = 0.f; g_bnsq[i] = 0.f; }
}

// ---------------- degree histogram ----------------
__global__ void k_hist(const int* __restrict__ dst) {
    int e = blockIdx.x * blockDim.x + threadIdx.x;
    if (e < E) atomicAdd(&g_deg[dst[e]], 1);
}

// ---------------- multi-block exclusive scan ----------------
__global__ void k_scan1() {
    __shared__ int ws[32];
    int t = threadIdx.x;
    int lane = t & 31, w = t >> 5;
    int base = blockIdx.x * 1024;
    int v = (base + t < N) ? g_deg[base + t] : 0;
    int x = v;
#pragma unroll
    for (int off = 1; off < 32; off <<= 1) {
        int y = __shfl_up_sync(0xffffffffu, x, off);
        if (lane >= off) x += y;
    }
    if (lane == 31) ws[w] = x;
    __syncthreads();
    if (w == 0) {
        int s = ws[lane];
#pragma unroll
        for (int off = 1; off < 32; off <<= 1) {
            int y = __shfl_up_sync(0xffffffffu, s, off);
            if (lane >= off) s += y;
        }
        ws[lane] = s;
    }
    __syncthreads();
    int incl = x + (w > 0 ? ws[w - 1] : 0);
    if (base + t < N) g_offs[base + t] = incl - v;
    if (t == 1023) g_btot[blockIdx.x] = incl;
}

__global__ void k_scan2() {
    if (threadIdx.x == 0) {
        int acc = 0;
        for (int i = 0; i < SCAN_BLOCKS; i++) {
            g_boff[i] = acc;
            acc += g_btot[i];
        }
    }
}

__global__ void k_scan3() {
    int t = threadIdx.x;
    int base = blockIdx.x * 1024;
    int off = g_boff[blockIdx.x];
    if (base + t < N) {
        int v = g_offs[base + t] + off;
        g_offs[base + t] = v;
        g_cursor[base + t] = v;
    }
    if (blockIdx.x == 0 && t == 0) g_offs[N] = E;
}

// ---------------- scatter: counting sort by dst ----------------
__global__ void k_scatter(const int* __restrict__ dst, const int* __restrict__ src) {
    int e = blockIdx.x * blockDim.x + threadIdx.x;
    if (e < E) {
        int pos = atomicAdd(&g_cursor[dst[e]], 1);
        g_perm[pos] = e;
        g_srcs[pos] = src[e];
    }
}

// ---------------- node pre-GEMMs via mma.sync -> fp16 g_A, g_B -------------------
constexpr int XP3 = 40;
constexpr int WP3 = 136;

__global__ void __launch_bounds__(256) k_nodepre()
{
    __shared__ __align__(16) __half Xs[128 * XP3];
    __shared__ __align__(16) __half Ws[32 * WP3];

    int tid = threadIdx.x;
    int base = blockIdx.x * 128;
    int w = tid >> 5;
    int l = tid & 31;
    int slab = w * 16;
    int r8 = l & 7;
    int mat = l >> 3;

    unsigned xsb = (unsigned)__cvta_generic_to_shared(Xs);
    unsigned wsb = (unsigned)__cvta_generic_to_shared(Ws);

    int xrow = tid >> 1;
    int xc0 = (tid & 1) * 16;
    int wk = tid >> 3;
    int wc0 = (tid & 7) * 16;

    float acc[16][4];

    // =========== phase h: K=128 ===========
#pragma unroll
    for (int j = 0; j < 16; j++)
#pragma unroll
        for (int q = 0; q < 4; q++) acc[j][q] = 0.f;

    for (int t = 0; t < 4; t++) {
        int k0 = t * 32;
        if (t) __syncthreads();
        {
            int n0 = base + xrow;
            __half* xd = Xs + xrow * XP3 + xc0;
            if (n0 < N) {
                const __half* rp = g_h16 + (size_t)n0 * 128 + k0 + xc0;
                *(uint4*)xd       = *(const uint4*)rp;
                *(uint4*)(xd + 8) = *(const uint4*)(rp + 8);
            } else {
                uint4 z = make_uint4(0, 0, 0, 0);
                *(uint4*)xd = z; *(uint4*)(xd + 8) = z;
            }
        }
        {
            const __half* wr = (wc0 < 64) ? (g_Wph16 + (size_t)(k0 + wk) * 64 + wc0)
                                          : (g_Wph16 + (size_t)(128 + k0 + wk) * 64 + (wc0 - 64));
            __half* wd = Ws + wk * WP3 + wc0;
            *(uint4*)wd       = *(const uint4*)wr;
            *(uint4*)(wd + 8) = *(const uint4*)(wr + 8);
        }
        __syncthreads();
#pragma unroll
        for (int kc = 0; kc < 2; kc++) {
            int arow = slab + r8 + ((mat & 1) ? 8 : 0);
            int acol = kc * 16 + ((mat & 2) ? 8 : 0);
            uint4 a = ldsm_x4(xsb + (unsigned)(arow * XP3 + acol) * 2u);
            int bk = kc * 16 + r8 + ((mat & 1) ? 8 : 0);
#pragma unroll
            for (int j = 0; j < 8; j++) {
                int bn = j * 16 + ((mat & 2) ? 8 : 0);
                uint4 b = ldsm_x4_t(wsb + (unsigned)(bk * WP3 + bn) * 2u);
                mma16816(acc[2 * j],     a, b.x, b.y);
                mma16816(acc[2 * j + 1], a, b.z, b.w);
            }
        }
    }
    {
        int r0 = slab + (l >> 2);
        int c0 = (l & 3) * 2;
        int n0 = base + r0, n1 = base + r0 + 8;
        bool v0 = n0 < N, v1 = n1 < N;
#pragma unroll
        for (int j = 0; j < 16; j++) {
            int col = 8 * j + c0;
            __half* d0;
            __half* d1;
            if (col < 64) {
                d0 = g_A + (size_t)n0 * 128 + col;
                d1 = g_A + (size_t)n1 * 128 + col;
            } else {
                d0 = g_B + (size_t)n0 * 128 + (col - 64);
                d1 = g_B + (size_t)n1 * 128 + (col - 64);
            }
            if (v0) *(__half2*)d0 = __floats2half2_rn(acc[j][0], acc[j][1]);
            if (v1) *(__half2*)d1 = __floats2half2_rn(acc[j][2], acc[j][3]);
        }
    }

    // =========== phase p: K=64 ===========
#pragma unroll
    for (int j = 0; j < 16; j++)
#pragma unroll
        for (int q = 0; q < 4; q++) acc[j][q] = 0.f;

    for (int t = 0; t < 2; t++) {
        int k0 = t * 32;
        __syncthreads();
        {
            int n0 = base + xrow;
            __half* xd = Xs + xrow * XP3 + xc0;
            if (n0 < N) {
                const __half* rp = g_p16 + (size_t)n0 * 64 + k0 + xc0;
                *(uint4*)xd       = *(const uint4*)rp;
                *(uint4*)(xd + 8) = *(const uint4*)(rp + 8);
            } else {
                uint4 z = make_uint4(0, 0, 0, 0);
                *(uint4*)xd = z; *(uint4*)(xd + 8) = z;
            }
        }
        {
            const __half* wr = (wc0 < 64) ? (g_Wpp16 + (size_t)(k0 + wk) * 64 + wc0)
                                          : (g_Wpp16 + (size_t)(64 + k0 + wk) * 64 + (wc0 - 64));
            __half* wd = Ws + wk * WP3 + wc0;
            *(uint4*)wd       = *(const uint4*)wr;
            *(uint4*)(wd + 8) = *(const uint4*)(wr + 8);
        }
        __syncthreads();
#pragma unroll
        for (int kc = 0; kc < 2; kc++) {
            int arow = slab + r8 + ((mat & 1) ? 8 : 0);
            int acol = kc * 16 + ((mat & 2) ? 8 : 0);
            uint4 a = ldsm_x4(xsb + (unsigned)(arow * XP3 + acol) * 2u);
            int bk = kc * 16 + r8 + ((mat & 1) ? 8 : 0);
#pragma unroll
            for (int j = 0; j < 8; j++) {
                int bn = j * 16 + ((mat & 2) ? 8 : 0);
                uint4 b = ldsm_x4_t(wsb + (unsigned)(bk * WP3 + bn) * 2u);
                mma16816(acc[2 * j],     a, b.x, b.y);
                mma16816(acc[2 * j + 1], a, b.z, b.w);
            }
        }
    }
    {
        int r0 = slab + (l >> 2);
        int c0 = (l & 3) * 2;
        int n0 = base + r0, n1 = base + r0 + 8;
        bool v0 = n0 < N, v1 = n1 < N;
#pragma unroll
        for (int j = 0; j < 16; j++) {
            int col = 8 * j + c0;
            __half* d0;
            __half* d1;
            if (col < 64) {
                d0 = g_A + (size_t)n0 * 128 + 64 + col;
                d1 = g_A + (size_t)n1 * 128 + 64 + col;
            } else {
                d0 = g_B + (size_t)n0 * 128 + col;
                d1 = g_B + (size_t)n1 * 128 + col;
            }
            if (v0) *(__half2*)d0 = __floats2half2_rn(acc[j][0], acc[j][1]);
            if (v1) *(__half2*)d1 = __floats2half2_rn(acc[j][2], acc[j][3]);
        }
    }
}

// ---------------- edge-feature GEMM via mma.sync (tensor cores) ------------------
constexpr int XP = 40;
constexpr int WP = 136;

__global__ void __launch_bounds__(256) k_edgeE(
    const float* __restrict__ ef,
    const float* __restrict__ bh, const float* __restrict__ bp)
{
    __shared__ __align__(16) __half Xs[128 * XP];
    __shared__ __align__(16) __half Ws[32 * WP];
    __shared__ float bias[128];

    int tid = threadIdx.x;
    int base = blockIdx.x * 128;
    int w = tid >> 5;
    int l = tid & 31;

    {
        int row = tid >> 1;
        int c0 = (tid & 1) * 16;
        const float* rowp = ef + (size_t)(base + row) * 32 + c0;
        __half* xd = Xs + row * XP + c0;
#pragma unroll
        for (int q = 0; q < 4; q++) {
            float4 a = *(const float4*)(rowp + q * 4);
            *(__half2*)(xd + q * 4)     = __floats2half2_rn(a.x, a.y);
            *(__half2*)(xd + q * 4 + 2) = __floats2half2_rn(a.z, a.w);
        }
    }
    {
        int k = tid >> 3;
        int c0 = (tid & 7) * 16;
        const __half* wr = (c0 < 64) ? (g_Wph16 + (size_t)(256 + k) * 64 + c0)
                                     : (g_Wpp16 + (size_t)(128 + k) * 64 + (c0 - 64));
        __half* wd = Ws + k * WP + c0;
        *(uint4*)wd       = *(const uint4*)wr;
        *(uint4*)(wd + 8) = *(const uint4*)(wr + 8);
    }
    if (tid < 128) bias[tid] = (tid < 64) ? bh[tid] : bp[tid - 64];
    __syncthreads();

    float acc[16][4];
#pragma unroll
    for (int j = 0; j < 16; j++)
#pragma unroll
        for (int q = 0; q < 4; q++) acc[j][q] = 0.f;

    int slab = w * 16;
    int r8 = l & 7;
    int mat = l >> 3;

    unsigned xsbase = (unsigned)__cvta_generic_to_shared(Xs);
    unsigned wsbase = (unsigned)__cvta_generic_to_shared(Ws);

#pragma unroll
    for (int kc = 0; kc < 2; kc++) {
        int arow = slab + r8 + ((mat & 1) ? 8 : 0);
        int acol = kc * 16 + ((mat & 2) ? 8 : 0);
        uint4 a = ldsm_x4(xsbase + (unsigned)(arow * XP + acol) * 2u);
#pragma unroll
        for (int j = 0; j < 8; j++) {
            int bk = kc * 16 + r8 + ((mat & 1) ? 8 : 0);
            int bn = j * 16 + ((mat & 2) ? 8 : 0);
            uint4 b = ldsm_x4_t(wsbase + (unsigned)(bk * WP + bn) * 2u);
            mma16816(acc[2 * j],     a, b.x, b.y);
            mma16816(acc[2 * j + 1], a, b.z, b.w);
        }
    }

    int r0 = slab + (l >> 2);
    int c0 = (l & 3) * 2;
    __half* out0 = g_ce + (size_t)(base + r0) * 128;
    __half* out1 = g_ce + (size_t)(base + r0 + 8) * 128;
#pragma unroll
    for (int j = 0; j < 16; j++) {
        int col = 8 * j + c0;
        float bz0 = bias[col], bz1 = bias[col + 1];
        *(__half2*)(out0 + col) = __floats2half2_rn(acc[j][0] + bz0, acc[j][1] + bz1);
        *(__half2*)(out1 + col) = __floats2half2_rn(acc[j][2] + bz0, acc[j][3] + bz1);
    }
}

// ---------------- fused message + PNA aggregation ----------------
// Lane l owns 4 CONSECUTIVE features: halfs [4l, 4l+4). Whole warp on one edge.
// ce gathers use streaming (.cs) hint so L2 keeps the hot g_A table resident.
__global__ void k_agg() {
    int warp = (blockIdx.x * blockDim.x + threadIdx.x) >> 5;
    int l = threadIdx.x & 31;
    if (warp >= N) return;
    int n = warp;
    int s0 = g_offs[n];
    int s1 = g_offs[n + 1];
    int d = s1 - s0;

    int off4 = 4 * l;
    float4 bv = ldh4(g_B + (size_t)n * 128 + off4);

    float4 sm = make_float4(0.f, 0.f, 0.f, 0.f);
    float4 sq = make_float4(0.f, 0.f, 0.f, 0.f);
    float4 mx = make_float4(-FLT_BIG, -FLT_BIG, -FLT_BIG, -FLT_BIG);
    float4 mn = make_float4(FLT_BIG, FLT_BIG, FLT_BIG, FLT_BIG);

#define AGG_ACC(CV, AV)                                                          \
    do {                                                                         \
        float v0 = (CV).x + (AV).x + bv.x;                                       \
        float v1 = (CV).y + (AV).y + bv.y;                                       \
        float v2 = (CV).z + (AV).z + bv.z;                                       \
        float v3 = (CV).w + (AV).w + bv.w;                                       \
        sm.x += v0; sq.x += v0 * v0; mx.x = fmaxf(mx.x, v0); mn.x = fminf(mn.x, v0); \
        sm.y += v1; sq.y += v1 * v1; mx.y = fmaxf(mx.y, v1); mn.y = fminf(mn.y, v1); \
        sm.z += v2; sq.z += v2 * v2; mx.z = fmaxf(mx.z, v2); mn.z = fminf(mn.z, v2); \
        sm.w += v3; sq.w += v3 * v3; mx.w = fmaxf(mx.w, v3); mn.w = fminf(mn.w, v3); \
    } while (0)

    int i = s0;
    if ((s1 - s0) & 1) {
        int s = g_srcs[i];
        int eid = g_perm[i];
        uint2 uc = __ldcs((const uint2*)(g_ce + (size_t)eid * 128 + off4));
        float4 cv = ldh4((const __half*)&uc);
        float4 av = ldh4(g_A + (size_t)s * 128 + off4);
        AGG_ACC(cv, av);
        i++;
    }
    for (; i < s1; i += 2) {
        int sA = g_srcs[i],   sB = g_srcs[i + 1];
        int eA = g_perm[i],   eB = g_perm[i + 1];
        uint2 uCA = __ldcs((const uint2*)(g_ce + (size_t)eA * 128 + off4));
        uint2 uAA = *(const uint2*)(g_A + (size_t)sA * 128 + off4);
        uint2 uCB = __ldcs((const uint2*)(g_ce + (size_t)eB * 128 + off4));
        uint2 uAB = *(const uint2*)(g_A + (size_t)sB * 128 + off4);
        {
            __half2 lo = *reinterpret_cast<__half2*>(&uCA.x);
            __half2 hi = *reinterpret_cast<__half2*>(&uCA.y);
            float2 c01 = __half22float2(lo), c23 = __half22float2(hi);
            lo = *reinterpret_cast<__half2*>(&uAA.x);
            hi = *reinterpret_cast<__half2*>(&uAA.y);
            float2 a01 = __half22float2(lo), a23 = __half22float2(hi);
            float4 cv = make_float4(c01.x, c01.y, c23.x, c23.y);
            float4 av = make_float4(a01.x, a01.y, a23.x, a23.y);
            AGG_ACC(cv, av);
        }
        {
            __half2 lo = *reinterpret_cast<__half2*>(&uCB.x);
            __half2 hi = *reinterpret_cast<__half2*>(&uCB.y);
            float2 c01 = __half22float2(lo), c23 = __half22float2(hi);
            lo = *reinterpret_cast<__half2*>(&uAB.x);
            hi = *reinterpret_cast<__half2*>(&uAB.y);
            float2 a01 = __half22float2(lo), a23 = __half22float2(hi);
            float4 cv = make_float4(c01.x, c01.y, c23.x, c23.y);
            float4 av = make_float4(a01.x, a01.y, a23.x, a23.y);
            AGG_ACC(cv, av);
        }
    }
#undef AGG_ACC

    float degc = fmaxf((float)d, 1.f);
    float inv = 1.f / degc;
    bool has = d > 0;
    float logd = has ? logf((float)d + 1.f) : 1.f;
    float amp = logd / AVG_D_LOG;
    float att = AVG_D_LOG / logd;
    if (l == 0) { g_amp[n] = amp; g_att[n] = att; }

    __half* o = (off4 < 64) ? (g_aggh + (size_t)n * 256) : (g_aggp + (size_t)n * 256);
    int f = off4 & 63;

    float4 mean = make_float4(sm.x * inv, sm.y * inv, sm.z * inv, sm.w * inv);
    float4 var = make_float4(fmaxf(sq.x * inv - mean.x * mean.x, 0.f),
                             fmaxf(sq.y * inv - mean.y * mean.y, 0.f),
                             fmaxf(sq.z * inv - mean.z * mean.z, 0.f),
                             fmaxf(sq.w * inv - mean.w * mean.w, 0.f));
    float4 sd = make_float4(sqrtf(var.x + EPS_STD), sqrtf(var.y + EPS_STD),
                            sqrtf(var.z + EPS_STD), sqrtf(var.w + EPS_STD));
    float4 MX = has ? mx : make_float4(0.f, 0.f, 0.f, 0.f);
    float4 MN = has ? mn : make_float4(0.f, 0.f, 0.f, 0.f);
    *(__half2*)(o + f)       = __floats2half2_rn(mean.x, mean.y);
    *(__half2*)(o + f + 2)   = __floats2half2_rn(mean.z, mean.w);
    *(__half2*)(o + 64 + f)     = __floats2half2_rn(MX.x, MX.y);
    *(__half2*)(o + 64 + f + 2) = __floats2half2_rn(MX.z, MX.w);
    *(__half2*)(o + 128 + f)     = __floats2half2_rn(MN.x, MN.y);
    *(__half2*)(o + 128 + f + 2) = __floats2half2_rn(MN.z, MN.w);
    *(__half2*)(o + 192 + f)     = __floats2half2_rn(sd.x, sd.y);
    *(__half2*)(o + 192 + f + 2) = __floats2half2_rn(sd.z, sd.w);
}

// ---------------- node GEMMs via mma.sync: 3 rails + fused BN stats -------------
constexpr int XP2 = 40;
constexpr int WP2 = 72;

__global__ void __launch_bounds__(256) k_nodegemm(
    const float* __restrict__ snorm,
    const float* __restrict__ boh, const float* __restrict__ bop,
    float* __restrict__ out)
{
    __shared__ __align__(16) __half Xs[128 * XP2];
    __shared__ __align__(16) __half Ws[3][32 * WP2];
    __shared__ float sbias[64];
    __shared__ float s_amp[128], s_att[128], s_sn[128];
    __shared__ float sbn[64], sbq[64];

    int tid = threadIdx.x;
    int base = blockIdx.x * 128;
    int w = tid >> 5;
    int l = tid & 31;
    int slab = w * 16;
    int r8 = l & 7;
    int mat = l >> 3;

    if (tid < 128) {
        int n0 = base + tid;
        bool ok = n0 < N;
        s_amp[tid] = ok ? g_amp[n0] : 0.f;
        s_att[tid] = ok ? g_att[n0] : 0.f;
        s_sn[tid]  = ok ? snorm[n0] : 0.f;
    }
    if (tid < 64) { sbn[tid] = 0.f; sbq[tid] = 0.f; sbias[tid] = boh[tid]; }

    unsigned xsb = (unsigned)__cvta_generic_to_shared(Xs);
    unsigned wsb0 = (unsigned)__cvta_generic_to_shared(&Ws[0][0]);
    unsigned wsb1 = (unsigned)__cvta_generic_to_shared(&Ws[1][0]);
    unsigned wsb2 = (unsigned)__cvta_generic_to_shared(&Ws[2][0]);

    float accI[8][4], accA[8][4], accT[8][4];

    int xrow = tid >> 1;
    int xc0 = (tid & 1) * 16;
    int wk = (tid * 8) >> 6;
    int wn = (tid * 8) & 63;

    // ================= phase H =================
#pragma unroll
    for (int j = 0; j < 8; j++)
#pragma unroll
        for (int q = 0; q < 4; q++) { accI[j][q] = 0.f; accA[j][q] = 0.f; accT[j][q] = 0.f; }

    for (int t = 0; t < 12; t++) {
        int k0 = t * 32;
        bool isAgg = (t >= 4);
        __syncthreads();
        {
            int n0 = base + xrow;
            __half* xd = Xs + xrow * XP2 + xc0;
            if (n0 < N) {
                const __half* rp = isAgg ? (g_aggh + (size_t)n0 * 256 + (k0 - 128) + xc0)
                                         : (g_h16 + (size_t)n0 * 128 + k0 + xc0);
                *(uint4*)xd       = *(const uint4*)rp;
                *(uint4*)(xd + 8) = *(const uint4*)(rp + 8);
            } else {
                uint4 z = make_uint4(0, 0, 0, 0);
                *(uint4*)xd = z; *(uint4*)(xd + 8) = z;
            }
        }
        {
            if (isAgg) {
                int aggk = k0 - 128;
                const __half* wI = g_Woh16 + (size_t)(128 + aggk + wk) * 64 + wn;
                const __half* wA = g_Woh16 + (size_t)(384 + aggk + wk) * 64 + wn;
                const __half* wT = g_Woh16 + (size_t)(640 + aggk + wk) * 64 + wn;
                *(uint4*)&Ws[0][wk * WP2 + wn] = *(const uint4*)wI;
                *(uint4*)&Ws[1][wk * WP2 + wn] = *(const uint4*)wA;
                *(uint4*)&Ws[2][wk * WP2 + wn] = *(const uint4*)wT;
            } else {
                const __half* wI = g_Woh16 + (size_t)(k0 + wk) * 64 + wn;
                *(uint4*)&Ws[0][wk * WP2 + wn] = *(const uint4*)wI;
            }
        }
        __syncthreads();
#pragma unroll
        for (int kc = 0; kc < 2; kc++) {
            int arow = slab + r8 + ((mat & 1) ? 8 : 0);
            int acol = kc * 16 + ((mat & 2) ? 8 : 0);
            uint4 a = ldsm_x4(xsb + (unsigned)(arow * XP2 + acol) * 2u);
            int bk = kc * 16 + r8 + ((mat & 1) ? 8 : 0);
#pragma unroll
            for (int j = 0; j < 4; j++) {
                int bn = j * 16 + ((mat & 2) ? 8 : 0);
                unsigned boff = (unsigned)(bk * WP2 + bn) * 2u;
                uint4 bI = ldsm_x4_t(wsb0 + boff);
                mma16816(accI[2 * j],     a, bI.x, bI.y);
                mma16816(accI[2 * j + 1], a, bI.z, bI.w);
                if (isAgg) {
                    uint4 bA = ldsm_x4_t(wsb1 + boff);
                    mma16816(accA[2 * j],     a, bA.x, bA.y);
                    mma16816(accA[2 * j + 1], a, bA.z, bA.w);
                    uint4 bT = ldsm_x4_t(wsb2 + boff);
                    mma16816(accT[2 * j],     a, bT.x, bT.y);
                    mma16816(accT[2 * j + 1], a, bT.z, bT.w);
                }
            }
        }
    }
    {
        int r0 = slab + (l >> 2);
        int c0l = (l & 3) * 2;
        int n0 = base + r0, n1 = base + r0 + 8;
        bool v0 = n0 < N, v1 = n1 < N;
        float amp0 = s_amp[r0], att0 = s_att[r0], sn0 = s_sn[r0];
        float amp1 = s_amp[r0 + 8], att1 = s_att[r0 + 8], sn1 = s_sn[r0 + 8];
#pragma unroll
        for (int j = 0; j < 8; j++) {
            int col = 8 * j + c0l;
            float b0 = sbias[col], b1 = sbias[col + 1];
            float y00 = (accI[j][0] + amp0 * accA[j][0] + att0 * accT[j][0] + b0) * sn0;
            float y01 = (accI[j][1] + amp0 * accA[j][1] + att0 * accT[j][1] + b1) * sn0;
            float y10 = (accI[j][2] + amp1 * accA[j][2] + att1 * accT[j][2] + b0) * sn1;
            float y11 = (accI[j][3] + amp1 * accA[j][3] + att1 * accT[j][3] + b1) * sn1;
            float ss0 = 0.f, ss1 = 0.f, qq0 = 0.f, qq1 = 0.f;
            if (v0) {
                *(float2*)&out[(size_t)n0 * 64 + col] = make_float2(y00, y01);
                ss0 += y00; ss1 += y01; qq0 += y00 * y00; qq1 += y01 * y01;
            }
            if (v1) {
                *(float2*)&out[(size_t)n1 * 64 + col] = make_float2(y10, y11);
                ss0 += y10; ss1 += y11; qq0 += y10 * y10; qq1 += y11 * y11;
            }
            atomicAdd(&sbn[col], ss0); atomicAdd(&sbn[col + 1], ss1);
            atomicAdd(&sbq[col], qq0); atomicAdd(&sbq[col + 1], qq1);
        }
    }
    __syncthreads();
    if (tid < 64) {
        atomicAdd(&g_bnsum[tid], sbn[tid]);
        atomicAdd(&g_bnsq[tid], sbq[tid]);
        sbias[tid] = bop[tid];
    }

    // ================= phase P =================
#pragma unroll
    for (int j = 0; j < 8; j++)
#pragma unroll
        for (int q = 0; q < 4; q++) { accI[j][q] = 0.f; accA[j][q] = 0.f; accT[j][q] = 0.f; }

    for (int t = 0; t < 10; t++) {
        int k0 = t * 32;
        bool isAgg = (t >= 2);
        __syncthreads();
        {
            int n0 = base + xrow;
            __half* xd = Xs + xrow * XP2 + xc0;
            if (n0 < N) {
                const __half* rp = isAgg ? (g_aggp + (size_t)n0 * 256 + (k0 - 64) + xc0)
                                         : (g_p16 + (size_t)n0 * 64 + k0 + xc0);
                *(uint4*)xd       = *(const uint4*)rp;
                *(uint4*)(xd + 8) = *(const uint4*)(rp + 8);
            } else {
                uint4 z = make_uint4(0, 0, 0, 0);
                *(uint4*)xd = z; *(uint4*)(xd + 8) = z;
            }
        }
        {
            if (isAgg) {
                int aggk = k0 - 64;
                const __half* wI = g_Wop16 + (size_t)(64 + aggk + wk) * 64 + wn;
                const __half* wA = g_Wop16 + (size_t)(320 + aggk + wk) * 64 + wn;
                const __half* wT = g_Wop16 + (size_t)(576 + aggk + wk) * 64 + wn;
                *(uint4*)&Ws[0][wk * WP2 + wn] = *(const uint4*)wI;
                *(uint4*)&Ws[1][wk * WP2 + wn] = *(const uint4*)wA;
                *(uint4*)&Ws[2][wk * WP2 + wn] = *(const uint4*)wT;
            } else {
                const __half* wI = g_Wop16 + (size_t)(k0 + wk) * 64 + wn;
                *(uint4*)&Ws[0][wk * WP2 + wn] = *(const uint4*)wI;
            }
        }
        __syncthreads();
#pragma unroll
        for (int kc = 0; kc < 2; kc++) {
            int arow = slab + r8 + ((mat & 1) ? 8 : 0);
            int acol = kc * 16 + ((mat & 2) ? 8 : 0);
            uint4 a = ldsm_x4(xsb + (unsigned)(arow * XP2 + acol) * 2u);
            int bk = kc * 16 + r8 + ((mat & 1) ? 8 : 0);
#pragma unroll
            for (int j = 0; j < 4; j++) {
                int bn = j * 16 + ((mat & 2) ? 8 : 0);
                unsigned boff = (unsigned)(bk * WP2 + bn) * 2u;
                uint4 bI = ldsm_x4_t(wsb0 + boff);
                mma16816(accI[2 * j],     a, bI.x, bI.y);
                mma16816(accI[2 * j + 1], a, bI.z, bI.w);
                if (isAgg) {
                    uint4 bA = ldsm_x4_t(wsb1 + boff);
                    mma16816(accA[2 * j],     a, bA.x, bA.y);
                    mma16816(accA[2 * j + 1], a, bA.z, bA.w);
                    uint4 bT = ldsm_x4_t(wsb2 + boff);
                    mma16816(accT[2 * j],     a, bT.x, bT.y);
                    mma16816(accT[2 * j + 1], a, bT.z, bT.w);
                }
            }
        }
    }
    {
        int r0 = slab + (l >> 2);
        int c0l = (l & 3) * 2;
        int n0 = base + r0, n1 = base + r0 + 8;
        float amp0 = s_amp[r0], att0 = s_att[r0];
        float amp1 = s_amp[r0 + 8], att1 = s_att[r0 + 8];
        float* outp = out + (size_t)N * 64;
#pragma unroll
        for (int j = 0; j < 8; j++) {
            int col = 8 * j + c0l;
            float b0 = sbias[col], b1 = sbias[col + 1];
            float y00 = accI[j][0] + amp0 * accA[j][0] + att0 * accT[j][0] + b0;
            float y01 = accI[j][1] + amp0 * accA[j][1] + att0 * accT[j][1] + b1;
            float y10 = accI[j][2] + amp1 * accA[j][2] + att1 * accT[j][2] + b0;
            float y11 = accI[j][3] + amp1 * accA[j][3] + att1 * accT[j][3] + b1;
            if (n0 < N) *(float2*)&outp[(size_t)n0 * 64 + col] = make_float2(y00, y01);
            if (n1 < N) *(float2*)&outp[(size_t)n1 * 64 + col] = make_float2(y10, y11);
        }
    }
}

// ---------------- batchnorm apply (float4 vectorized) ----------------
__global__ void k_bnapply(float* __restrict__ out,
                          const float* __restrict__ gamma,
                          const float* __restrict__ beta) {
    int i = blockIdx.x * blockDim.x + threadIdx.x;
    if (i >= N * 16) return;
    int f = (i & 15) * 4;
    const float invN = 1.f / (float)N;
    float4 su = *(const float4*)&g_bnsum[f];
    float4 qu = *(const float4*)&g_bnsq[f];
    float4 ga = *(const float4*)&gamma[f];
    float4 be = *(const float4*)&beta[f];
    float4 mu = make_float4(su.x * invN, su.y * invN, su.z * invN, su.w * invN);
    float4 rs = make_float4(
        rsqrtf(qu.x * invN - mu.x * mu.x + EPS_BN),
        rsqrtf(qu.y * invN - mu.y * mu.y + EPS_BN),
        rsqrtf(qu.z * invN - mu.z * mu.z + EPS_BN),
        rsqrtf(qu.w * invN - mu.w * mu.w + EPS_BN));
    float4 x = *(float4*)&out[(size_t)i * 4];
    x.x = (x.x - mu.x) * rs.x * ga.x + be.x;
    x.y = (x.y - mu.y) * rs.y * ga.y + be.y;
    x.z = (x.z - mu.z) * rs.z * ga.z + be.z;
    x.w = (x.w - mu.w) * rs.w * ga.w + be.w;
    *(float4*)&out[(size_t)i * 4] = x;
}

} // namespace

extern "C" void kernel_launch(void* const* d_in, const int* in_sizes, int n_in,
                              void* d_out, int out_size) {
    const float* h     = (const float*)d_in[0];
    const float* p     = (const float*)d_in[1];
    const float* e     = (const float*)d_in[2];
    const int*   src   = (const int*)d_in[3];
    const int*   dst   = (const int*)d_in[4];
    const float* snorm = (const float*)d_in[5];
    const float* Wph   = (const float*)d_in[6];
    const float* bph   = (const float*)d_in[7];
    const float* Wpp   = (const float*)d_in[8];
    const float* bpp   = (const float*)d_in[9];
    const float* Woh   = (const float*)d_in[10];
    const float* boh   = (const float*)d_in[11];
    const float* Wop   = (const float*)d_in[12];
    const float* bop   = (const float*)d_in[13];
    const float* gamma = (const float*)d_in[14];
    const float* beta  = (const float*)d_in[15];
    float* out = (float*)d_out;

    static cudaStream_t s_pre = nullptr, s_edge = nullptr;
    static cudaEvent_t ev_fork = nullptr, ev_cvt = nullptr, ev_pre = nullptr, ev_edge = nullptr;
    if (s_pre == nullptr) {
        cudaStreamCreateWithFlags(&s_pre, cudaStreamNonBlocking);
        cudaStreamCreateWithFlags(&s_edge, cudaStreamNonBlocking);
        cudaEventCreateWithFlags(&ev_fork, cudaEventDisableTiming);
        cudaEventCreateWithFlags(&ev_cvt, cudaEventDisableTiming);
        cudaEventCreateWithFlags(&ev_pre, cudaEventDisableTiming);
        cudaEventCreateWithFlags(&ev_edge, cudaEventDisableTiming);
    }

    cudaEventRecord(ev_fork, 0);
    cudaStreamWaitEvent(s_pre, ev_fork, 0);
    cudaStreamWaitEvent(s_edge, ev_fork, 0);

    // side stream 1: fp16 pre-conversion, then node pre-GEMMs
    k_cvt_w<<<64, 256, 0, s_pre>>>(Wph, Wpp, Woh, Wop);
    k_cvt_feat<<<1024, 256, 0, s_pre>>>(h, p);
    cudaEventRecord(ev_cvt, s_pre);
    k_nodepre<<<(N + 127) / 128, 256, 0, s_pre>>>();
    cudaEventRecord(ev_pre, s_pre);

    // side stream 2: edge-feature GEMM (needs fp16 weights)
    cudaStreamWaitEvent(s_edge, ev_cvt, 0);
    k_edgeE<<<E / 128, 256, 0, s_edge>>>(e, bph, bpp);
    cudaEventRecord(ev_edge, s_edge);

    // main stream: CSR construction
    k_init<<<(N + 255) / 256, 256>>>();
    k_hist<<<(E + 255) / 256, 256>>>(dst);
    k_scan1<<<SCAN_BLOCKS, 1024>>>();
    k_scan2<<<1, 32>>>();
    k_scan3<<<SCAN_BLOCKS, 1024>>>();
    k_scatter<<<(E + 255) / 256, 256>>>(dst, src);

    cudaStreamWaitEvent(0, ev_pre, 0);
    cudaStreamWaitEvent(0, ev_edge, 0);
    k_agg<<<(N * 32 + 255) / 256, 256>>>();
    k_nodegemm<<<(N + 127) / 128, 256>>>(snorm, boh, bop, out);
    k_bnapply<<<(N * 16 + 255) / 256, 256>>>(out, gamma, beta);
}